// round 8
// baseline (speedup 1.0000x reference)
#include <cuda_runtime.h>
#include <math.h>
#include <stdint.h>

// Problem constants
#define BB 32
#define TT 12
#define NS 325
#define DD 128
#define FF 512
#define MTOK (BB*TT*NS)   // 124800 tokens = 487*256 + 128
#define MMAIN 487
#define TOFF ((size_t)MMAIN * 256)   // 124672

// ---------------- scratch (static device allocations; no runtime alloc) ------
__device__ float g_buf  [(size_t)MTOK * 512];
__device__ float g_attn [(size_t)MTOK * 128];
__device__ float g_x1   [(size_t)MTOK * 128];
__device__ float g_x2   [(size_t)MTOK * 128];

// ---------------- helpers ----------------------------------------------------
__device__ __forceinline__ float gelu_tanh(float x) {
    float x3 = x * x * x;
    float t  = tanhf(0.7978845608028654f * (x + 0.044715f * x3));
    return 0.5f * x * (1.0f + t);
}

__device__ __forceinline__ uint32_t f2tf32(float x) {
    uint32_t r;
    asm("cvt.rna.tf32.f32 %0, %1;" : "=r"(r) : "f"(x));
    return r;
}

__device__ __forceinline__ void mma_tf32(float c[4], const uint32_t a[4], const uint32_t b[2]) {
    asm volatile(
        "mma.sync.aligned.m16n8k8.row.col.f32.tf32.tf32.f32 "
        "{%0,%1,%2,%3}, {%4,%5,%6,%7}, {%8,%9}, {%0,%1,%2,%3};"
        : "+f"(c[0]), "+f"(c[1]), "+f"(c[2]), "+f"(c[3])
        : "r"(a[0]), "r"(a[1]), "r"(a[2]), "r"(a[3]), "r"(b[0]), "r"(b[1]));
}

__device__ __forceinline__ void cp_async16(uint32_t smem_addr, const void* gptr) {
    asm volatile("cp.async.cg.shared.global [%0], [%1], 16;\n"
                 :: "r"(smem_addr), "l"(gptr));
}
__device__ __forceinline__ void cp_commit() {
    asm volatile("cp.async.commit_group;\n" ::: "memory");
}
template<int N>
__device__ __forceinline__ void cp_wait() {
    asm volatile("cp.async.wait_group %0;\n" :: "n"(N) : "memory");
}

// ---------------- TF32 tensor-core GEMM, cp.async 3-stage pipeline ------------
// C[M,N] = A[M,K] @ W[N,K]^T + bias, then optionally gelu (FFN1) or fused
// residual+LayerNorm (out-proj / FFN2; requires grid.x == 1, N == 128).
// CTA tile (MT*64) x 128, K chunk 32, 256 threads = 8 warps (4 on M x 2 on N),
// warp tile (MT*16) x 64. MT=4 -> 256x128 CTA tile: per-chunk fragment traffic
// 128KB per 1.05M MACs = 8.2 MAC/byte, at/above the 128B/cyc LDS crossbar
// break-even, so the tensor pipe (not smem) binds. MT=2 handles the M tail.
// GMEM->SMEM via cp.async.cg (raw fp32; mma.tf32 HW-truncates mantissa).
// k-slot remap (mma slot tg <-> physical k=2*tg) keeps every fragment operand
// pair a single LDS.64. 16B-block XOR swizzle per 32-word row.
template<int KDIM, int MT, bool DOGELU, bool FUSELN>
__global__ __launch_bounds__(256, 1) void gemm_tf32(
    const float* __restrict__ A, const float* __restrict__ W,
    const float* __restrict__ bias, float* __restrict__ C, int N,
    const float* __restrict__ Xres, const float* __restrict__ gamma,
    const float* __restrict__ beta) {
    extern __shared__ uint32_t sm[];
    constexpr int AW = MT * 2048;          // A words per stage ((MT*64)*32)
    constexpr int SW = AW + 4096;          // stage words (A + 128*32 B)

    const int tid  = threadIdx.x;
    const int warp = tid >> 5, lane = tid & 31;
    const int wm = warp & 3, wn = warp >> 2;
    const int g  = lane >> 2, tg = lane & 3;
    const int m0 = blockIdx.y * (MT * 64);
    const int n0 = blockIdx.x << 7;

    const int rr = tid >> 3;   // copy row base (0..31)
    const int bk = tid & 7;    // 16B block within 32-word row

    auto issue = [&](int c) {
        const int st = c % 3;
        const int k0 = c << 5;
        uint32_t baseA = (uint32_t)__cvta_generic_to_shared(&sm[st * SW]);
        uint32_t baseW = baseA + AW * 4;
#pragma unroll
        for (int i = 0; i < MT * 2; i++) {
            int r = rr + (i << 5);
            uint32_t off = ((r << 5) + ((bk ^ (r & 7)) << 2)) << 2;
            cp_async16(baseA + off, &A[(size_t)(m0 + r) * KDIM + k0 + (bk << 2)]);
        }
#pragma unroll
        for (int i = 0; i < 4; i++) {
            int r = rr + (i << 5);
            uint32_t off = ((r << 5) + ((bk ^ (r & 7)) << 2)) << 2;
            cp_async16(baseW + off, &W[(size_t)(n0 + r) * KDIM + k0 + (bk << 2)]);
        }
        cp_commit();
    };

    float acc[MT][8][4] = {};

    const int NC = KDIM / 32;
    issue(0);
    if (NC > 1) issue(1);

    for (int c = 0; c < NC; c++) {
        if (c == NC - 1) cp_wait<0>(); else cp_wait<1>();
        __syncthreads();
        if (c + 2 < NC) issue(c + 2);

        const uint32_t* As  = &sm[(c % 3) * SW];
        const uint32_t* Ws_ = As + AW;
#pragma unroll
        for (int ks = 0; ks < 4; ks++) {
            const int colw = (((2 * ks + (tg >> 1)) ^ g) << 2) + ((tg & 1) << 1);
            uint32_t afr[MT][4];
#pragma unroll
            for (int mt = 0; mt < MT; mt++) {
                int r = wm * (MT << 4) + (mt << 4) + g;
                uint2 p0 = *(const uint2*)&As[(r << 5) + colw];
                uint2 p1 = *(const uint2*)&As[((r + 8) << 5) + colw];
                afr[mt][0] = p0.x; afr[mt][1] = p1.x;
                afr[mt][2] = p0.y; afr[mt][3] = p1.y;
            }
#pragma unroll
            for (int nt = 0; nt < 8; nt++) {
                int rb = (wn << 6) + (nt << 3) + g;
                uint2 pb = *(const uint2*)&Ws_[(rb << 5) + colw];
                uint32_t bfr[2] = {pb.x, pb.y};
#pragma unroll
                for (int mt = 0; mt < MT; mt++)
                    mma_tf32(acc[mt][nt], afr[mt], bfr);
            }
        }
    }

    if (!FUSELN) {
#pragma unroll
        for (int mt = 0; mt < MT; mt++) {
            int row0 = m0 + wm * (MT << 4) + (mt << 4) + g;
#pragma unroll
            for (int nt = 0; nt < 8; nt++) {
                int col = n0 + (wn << 6) + (nt << 3) + (tg << 1);
                float b0 = __ldg(&bias[col]);
                float b1 = __ldg(&bias[col + 1]);
                float v00 = acc[mt][nt][0] + b0, v01 = acc[mt][nt][1] + b1;
                float v10 = acc[mt][nt][2] + b0, v11 = acc[mt][nt][3] + b1;
                if (DOGELU) {
                    v00 = gelu_tanh(v00); v01 = gelu_tanh(v01);
                    v10 = gelu_tanh(v10); v11 = gelu_tanh(v11);
                }
                *(float2*)&C[(size_t)row0 * N + col]       = make_float2(v00, v01);
                *(float2*)&C[(size_t)(row0 + 8) * N + col] = make_float2(v10, v11);
            }
        }
    } else {
        // fused residual + LayerNorm over the full 128-col row (n0 == 0).
        // v = acc + bias + Xres computed IN PLACE in acc; LN(v)*gamma+beta -> C.
        __syncthreads();                      // all warps done with smem stages
        float* red = (float*)sm;              // [MT*64 rows][2 wn][{sum,ss}]

        float psum[MT][2], pss[MT][2];
#pragma unroll
        for (int mt = 0; mt < MT; mt++)
#pragma unroll
            for (int rh = 0; rh < 2; rh++) {
                int row = m0 + wm * (MT << 4) + (mt << 4) + (rh << 3) + g;
                const float* xr = Xres + (size_t)row * 128;
                float s = 0.f, ss = 0.f;
#pragma unroll
                for (int nt = 0; nt < 8; nt++) {
                    int col = (wn << 6) + (nt << 3) + (tg << 1);
                    float2 xv = *(const float2*)&xr[col];
                    float b0 = __ldg(&bias[col]);
                    float b1 = __ldg(&bias[col + 1]);
                    float v0 = acc[mt][nt][rh * 2 + 0] + b0 + xv.x;
                    float v1 = acc[mt][nt][rh * 2 + 1] + b1 + xv.y;
                    acc[mt][nt][rh * 2 + 0] = v0;
                    acc[mt][nt][rh * 2 + 1] = v1;
                    s  += v0 + v1;
                    ss += v0 * v0 + v1 * v1;
                }
                s  += __shfl_xor_sync(0xffffffffu, s, 1);
                s  += __shfl_xor_sync(0xffffffffu, s, 2);
                ss += __shfl_xor_sync(0xffffffffu, ss, 1);
                ss += __shfl_xor_sync(0xffffffffu, ss, 2);
                psum[mt][rh] = s;
                pss[mt][rh]  = ss;
            }
#pragma unroll
        for (int mt = 0; mt < MT; mt++)
#pragma unroll
            for (int rh = 0; rh < 2; rh++) {
                int rl = wm * (MT << 4) + (mt << 4) + (rh << 3) + g;
                if (tg == 0) {
                    red[rl * 4 + wn * 2 + 0] = psum[mt][rh];
                    red[rl * 4 + wn * 2 + 1] = pss[mt][rh];
                }
            }
        __syncthreads();
#pragma unroll
        for (int mt = 0; mt < MT; mt++)
#pragma unroll
            for (int rh = 0; rh < 2; rh++) {
                int rl  = wm * (MT << 4) + (mt << 4) + (rh << 3) + g;
                float s  = red[rl * 4 + 0] + red[rl * 4 + 2];
                float ss = red[rl * 4 + 1] + red[rl * 4 + 3];
                float mean = s * (1.0f / 128.0f);
                float var  = ss * (1.0f / 128.0f) - mean * mean;
                float rstd = rsqrtf(var + 1e-5f);
                float* op = C + (size_t)(m0 + rl) * 128;
#pragma unroll
                for (int nt = 0; nt < 8; nt++) {
                    int col = (wn << 6) + (nt << 3) + (tg << 1);
                    float g0 = __ldg(&gamma[col]),     b0 = __ldg(&beta[col]);
                    float g1 = __ldg(&gamma[col + 1]), b1 = __ldg(&beta[col + 1]);
                    float o0 = (acc[mt][nt][rh * 2 + 0] - mean) * rstd * g0 + b0;
                    float o1 = (acc[mt][nt][rh * 2 + 1] - mean) * rstd * g1 + b1;
                    *(float2*)&op[col] = make_float2(o0, o1);
                }
            }
    }
}

#define SMEM_MT4 (3 * (4 * 2048 + 4096) * 4)   // 147456
#define SMEM_MT2 (3 * (2 * 2048 + 4096) * 4)   // 98304

// ---------------- temporal attention (seqlen T=12) ---------------------------
__global__ __launch_bounds__(96) void temporal_attn(
    const float* __restrict__ QKV, float* __restrict__ Out) {
    __shared__ float s[TT * 384];
    int n = blockIdx.x;
    int b = blockIdx.y;
    for (int idx = threadIdx.x; idx < TT * 384; idx += 96) {
        int t = idx / 384, c = idx % 384;
        s[idx] = QKV[((size_t)(b * TT + t) * NS + n) * 384 + c];
    }
    __syncthreads();

    int h = threadIdx.x / TT;
    int q = threadIdx.x % TT;

    float qr[16];
#pragma unroll
    for (int d = 0; d < 16; d++) qr[d] = s[q * 384 + h * 16 + d];

    float sc[TT];
    float mx = -1e30f;
#pragma unroll
    for (int t2 = 0; t2 < TT; t2++) {
        const float* kr = &s[t2 * 384 + 128 + h * 16];
        float dot = 0.f;
#pragma unroll
        for (int d = 0; d < 16; d++) dot += qr[d] * kr[d];
        sc[t2] = dot * 0.25f;
        mx = fmaxf(mx, sc[t2]);
    }
    float l = 0.f;
#pragma unroll
    for (int t2 = 0; t2 < TT; t2++) {
        sc[t2] = __expf(sc[t2] - mx);
        l += sc[t2];
    }
    float acc[16] = {};
#pragma unroll
    for (int t2 = 0; t2 < TT; t2++) {
        float p = sc[t2];
        const float* vr = &s[t2 * 384 + 256 + h * 16];
#pragma unroll
        for (int d = 0; d < 16; d++) acc[d] += p * vr[d];
    }
    float inv = 1.f / l;
    float* op = &Out[((size_t)(b * TT + q) * NS + n) * 128 + h * 16];
#pragma unroll
    for (int d = 0; d < 16; d++) op[d] = acc[d] * inv;
}

// ---------------- spatial attention via tensor cores -------------------------
__global__ __launch_bounds__(128) void spatial_attn_mma(
    const float* __restrict__ QKV, const float* __restrict__ Bias,
    float* __restrict__ Out) {
    __shared__ uint32_t Ks [328 * 20];
    __shared__ uint32_t Vst[16 * 332];
    const int h  = blockIdx.x;
    const int bt = blockIdx.y;
    const size_t base = (size_t)bt * NS;
    const int tid = threadIdx.x;

    for (int idx = tid; idx < 328 * 16; idx += 128) {
        int key = idx >> 4, d = idx & 15;
        float kv = 0.f, vv = 0.f;
        if (key < NS) {
            const float* p = QKV + (base + key) * 384 + h * 16 + d;
            kv = p[128];
            vv = p[256];
        }
        Ks [key * 20 + d]   = f2tf32(kv);
        Vst[d * 332 + key]  = f2tf32(vv);
    }
    __syncthreads();

    const int warp = tid >> 5, lane = tid & 31;
    const int g = lane >> 2, tg = lane & 3;

    for (int qt = 0; qt < 6; qt++) {
        const int q0 = qt * 64 + warp * 16;
        if (q0 >= NS) break;

        const float* Qp0 = QKV + (base + q0 + g) * 384 + h * 16;
        const float* Qp1 = Qp0 + 8 * 384;
        float2 q00 = *(const float2*)(Qp0 + 2 * tg);
        float2 q01 = *(const float2*)(Qp0 + 8 + 2 * tg);
        float2 q10 = *(const float2*)(Qp1 + 2 * tg);
        float2 q11 = *(const float2*)(Qp1 + 8 + 2 * tg);
        uint32_t qa0[4] = {f2tf32(q00.x), f2tf32(q10.x), f2tf32(q00.y), f2tf32(q10.y)};
        uint32_t qa1[4] = {f2tf32(q01.x), f2tf32(q11.x), f2tf32(q01.y), f2tf32(q11.y)};

        const int qr0 = min(q0 + g, NS - 1);
        const int qr1 = min(q0 + g + 8, NS - 1);
        const float* brow0 = Bias + (size_t)qr0 * NS;
        const float* brow1 = Bias + (size_t)qr1 * NS;

        float o0[4] = {0.f, 0.f, 0.f, 0.f};
        float o1[4] = {0.f, 0.f, 0.f, 0.f};
        float l0 = 0.f, l1 = 0.f;

        for (int nt = 0; nt < 40; nt++) {
            const int k0 = nt * 8;
            float c[4] = {0.f, 0.f, 0.f, 0.f};
            {
                uint2 b = *(const uint2*)&Ks[(k0 + g) * 20 + 2 * tg];
                uint32_t bf[2] = {b.x, b.y};
                mma_tf32(c, qa0, bf);
            }
            {
                uint2 b = *(const uint2*)&Ks[(k0 + g) * 20 + 8 + 2 * tg];
                uint32_t bf[2] = {b.x, b.y};
                mma_tf32(c, qa1, bf);
            }
            const int col0 = k0 + 2 * tg;
            float p0 = __expf(c[0] * 0.25f + __ldg(brow0 + col0));
            float p1 = __expf(c[1] * 0.25f + __ldg(brow0 + col0 + 1));
            float p2 = __expf(c[2] * 0.25f + __ldg(brow1 + col0));
            float p3 = __expf(c[3] * 0.25f + __ldg(brow1 + col0 + 1));
            l0 += p0 + p1;
            l1 += p2 + p3;
            uint32_t pa[4] = {f2tf32(p0), f2tf32(p2), f2tf32(p1), f2tf32(p3)};
            {
                uint2 vb = *(const uint2*)&Vst[g * 332 + col0];
                uint32_t bf[2] = {vb.x, vb.y};
                mma_tf32(o0, pa, bf);
            }
            {
                uint2 vb = *(const uint2*)&Vst[(8 + g) * 332 + col0];
                uint32_t bf[2] = {vb.x, vb.y};
                mma_tf32(o1, pa, bf);
            }
        }
        {
            const int k0 = 320;
            float c[4] = {0.f, 0.f, 0.f, 0.f};
            {
                uint2 b = *(const uint2*)&Ks[(k0 + g) * 20 + 2 * tg];
                uint32_t bf[2] = {b.x, b.y};
                mma_tf32(c, qa0, bf);
            }
            {
                uint2 b = *(const uint2*)&Ks[(k0 + g) * 20 + 8 + 2 * tg];
                uint32_t bf[2] = {b.x, b.y};
                mma_tf32(c, qa1, bf);
            }
            const int col0 = k0 + 2 * tg;
            const int col1 = col0 + 1;
            float p0 = (col0 < NS) ? __expf(c[0] * 0.25f + __ldg(brow0 + col0)) : 0.f;
            float p1 = (col1 < NS) ? __expf(c[1] * 0.25f + __ldg(brow0 + col1)) : 0.f;
            float p2 = (col0 < NS) ? __expf(c[2] * 0.25f + __ldg(brow1 + col0)) : 0.f;
            float p3 = (col1 < NS) ? __expf(c[3] * 0.25f + __ldg(brow1 + col1)) : 0.f;
            l0 += p0 + p1;
            l1 += p2 + p3;
            uint32_t pa[4] = {f2tf32(p0), f2tf32(p2), f2tf32(p1), f2tf32(p3)};
            {
                uint2 vb = *(const uint2*)&Vst[g * 332 + col0];
                uint32_t bf[2] = {vb.x, vb.y};
                mma_tf32(o0, pa, bf);
            }
            {
                uint2 vb = *(const uint2*)&Vst[(8 + g) * 332 + col0];
                uint32_t bf[2] = {vb.x, vb.y};
                mma_tf32(o1, pa, bf);
            }
        }

        l0 += __shfl_xor_sync(0xffffffffu, l0, 1);
        l0 += __shfl_xor_sync(0xffffffffu, l0, 2);
        l1 += __shfl_xor_sync(0xffffffffu, l1, 1);
        l1 += __shfl_xor_sync(0xffffffffu, l1, 2);
        float inv0 = 1.f / l0;
        float inv1 = 1.f / l1;

        if (q0 + g < NS) {
            float* op = Out + (base + q0 + g) * 128 + h * 16;
            *(float2*)(op + 2 * tg)     = make_float2(o0[0] * inv0, o0[1] * inv0);
            *(float2*)(op + 8 + 2 * tg) = make_float2(o1[0] * inv0, o1[1] * inv0);
        }
        if (q0 + g + 8 < NS) {
            float* op = Out + (base + q0 + g + 8) * 128 + h * 16;
            *(float2*)(op + 2 * tg)     = make_float2(o0[2] * inv1, o0[3] * inv1);
            *(float2*)(op + 8 + 2 * tg) = make_float2(o1[2] * inv1, o1[3] * inv1);
        }
    }
}

// ---------------- driver ------------------------------------------------------
extern "C" void kernel_launch(void* const* d_in, const int* in_sizes, int n_in,
                              void* d_out, int out_size) {
    const float* x        = (const float*)d_in[0];
    const float* t_w_in   = (const float*)d_in[1];
    const float* t_b_in   = (const float*)d_in[2];
    const float* t_w_out  = (const float*)d_in[3];
    const float* t_b_out  = (const float*)d_in[4];
    const float* s_w_in   = (const float*)d_in[5];
    const float* s_b_in   = (const float*)d_in[6];
    const float* s_w_out  = (const float*)d_in[7];
    const float* s_b_out  = (const float*)d_in[8];
    const float* g_bias   = (const float*)d_in[9];
    const float* norm_t_g = (const float*)d_in[10];
    const float* norm_t_b = (const float*)d_in[11];
    const float* norm_s_g = (const float*)d_in[12];
    const float* norm_s_b = (const float*)d_in[13];
    const float* ff_w1    = (const float*)d_in[14];
    const float* ff_b1    = (const float*)d_in[15];
    const float* ff_w2    = (const float*)d_in[16];
    const float* ff_b2    = (const float*)d_in[17];
    const float* norm_f_g = (const float*)d_in[18];
    const float* norm_f_b = (const float*)d_in[19];
    float* out = (float*)d_out;

    float *buf, *attn, *x1, *x2;
    cudaGetSymbolAddress((void**)&buf,  g_buf);
    cudaGetSymbolAddress((void**)&attn, g_attn);
    cudaGetSymbolAddress((void**)&x1,   g_x1);
    cudaGetSymbolAddress((void**)&x2,   g_x2);

    cudaFuncSetAttribute(gemm_tf32<128, 4, false, false>, cudaFuncAttributeMaxDynamicSharedMemorySize, SMEM_MT4);
    cudaFuncSetAttribute(gemm_tf32<128, 2, false, false>, cudaFuncAttributeMaxDynamicSharedMemorySize, SMEM_MT2);
    cudaFuncSetAttribute(gemm_tf32<128, 4, false, true >, cudaFuncAttributeMaxDynamicSharedMemorySize, SMEM_MT4);
    cudaFuncSetAttribute(gemm_tf32<128, 2, false, true >, cudaFuncAttributeMaxDynamicSharedMemorySize, SMEM_MT2);
    cudaFuncSetAttribute(gemm_tf32<128, 4, true,  false>, cudaFuncAttributeMaxDynamicSharedMemorySize, SMEM_MT4);
    cudaFuncSetAttribute(gemm_tf32<128, 2, true,  false>, cudaFuncAttributeMaxDynamicSharedMemorySize, SMEM_MT2);
    cudaFuncSetAttribute(gemm_tf32<512, 4, false, true >, cudaFuncAttributeMaxDynamicSharedMemorySize, SMEM_MT4);
    cudaFuncSetAttribute(gemm_tf32<512, 2, false, true >, cudaFuncAttributeMaxDynamicSharedMemorySize, SMEM_MT2);

    // --- temporal block: QKV ---
    gemm_tf32<128, 4, false, false><<<dim3(3, MMAIN), 256, SMEM_MT4>>>(
        x, t_w_in, t_b_in, buf, 384, nullptr, nullptr, nullptr);
    gemm_tf32<128, 2, false, false><<<dim3(3, 1), 256, SMEM_MT2>>>(
        x + TOFF * 128, t_w_in, t_b_in, buf + TOFF * 384, 384, nullptr, nullptr, nullptr);
    temporal_attn<<<dim3(NS, BB), 96>>>(buf, attn);
    // --- temporal out-proj + residual + LN ---
    gemm_tf32<128, 4, false, true><<<dim3(1, MMAIN), 256, SMEM_MT4>>>(
        attn, t_w_out, t_b_out, x1, 128, x, norm_t_g, norm_t_b);
    gemm_tf32<128, 2, false, true><<<dim3(1, 1), 256, SMEM_MT2>>>(
        attn + TOFF * 128, t_w_out, t_b_out, x1 + TOFF * 128, 128,
        x + TOFF * 128, norm_t_g, norm_t_b);

    // --- spatial block: QKV ---
    gemm_tf32<128, 4, false, false><<<dim3(3, MMAIN), 256, SMEM_MT4>>>(
        x1, s_w_in, s_b_in, buf, 384, nullptr, nullptr, nullptr);
    gemm_tf32<128, 2, false, false><<<dim3(3, 1), 256, SMEM_MT2>>>(
        x1 + TOFF * 128, s_w_in, s_b_in, buf + TOFF * 384, 384, nullptr, nullptr, nullptr);
    spatial_attn_mma<<<dim3(8, BB * TT), 128>>>(buf, g_bias, attn);
    // --- spatial out-proj + residual + LN ---
    gemm_tf32<128, 4, false, true><<<dim3(1, MMAIN), 256, SMEM_MT4>>>(
        attn, s_w_out, s_b_out, x2, 128, x1, norm_s_g, norm_s_b);
    gemm_tf32<128, 2, false, true><<<dim3(1, 1), 256, SMEM_MT2>>>(
        attn + TOFF * 128, s_w_out, s_b_out, x2 + TOFF * 128, 128,
        x1 + TOFF * 128, norm_s_g, norm_s_b);

    // --- FFN ---
    gemm_tf32<128, 4, true, false><<<dim3(4, MMAIN), 256, SMEM_MT4>>>(
        x2, ff_w1, ff_b1, buf, 512, nullptr, nullptr, nullptr);
    gemm_tf32<128, 2, true, false><<<dim3(4, 1), 256, SMEM_MT2>>>(
        x2 + TOFF * 128, ff_w1, ff_b1, buf + TOFF * 512, 512, nullptr, nullptr, nullptr);
    gemm_tf32<512, 4, false, true><<<dim3(1, MMAIN), 256, SMEM_MT4>>>(
        buf, ff_w2, ff_b2, out, 128, x2, norm_f_g, norm_f_b);
    gemm_tf32<512, 2, false, true><<<dim3(1, 1), 256, SMEM_MT2>>>(
        buf + TOFF * 512, ff_w2, ff_b2, out + TOFF * 128, 128,
        x2 + TOFF * 128, norm_f_g, norm_f_b);
}

// round 10
// speedup vs baseline: 1.1276x; 1.1276x over previous
#include <cuda_runtime.h>
#include <math.h>
#include <stdint.h>

// Problem constants
#define BB 32
#define TT 12
#define NS 325
#define DD 128
#define FF 512
#define MTOK (BB*TT*NS)   // 124800 tokens = 975 * 128 exactly

// ---------------- scratch (static device allocations; no runtime alloc) ------
__device__ float g_buf  [(size_t)MTOK * 512];
__device__ float g_attn [(size_t)MTOK * 128];
__device__ float g_x1   [(size_t)MTOK * 128];
__device__ float g_x2   [(size_t)MTOK * 128];

// ---------------- helpers ----------------------------------------------------
__device__ __forceinline__ float gelu_tanh(float x) {
    float x3 = x * x * x;
    float t  = tanhf(0.7978845608028654f * (x + 0.044715f * x3));
    return 0.5f * x * (1.0f + t);
}

__device__ __forceinline__ uint32_t f2tf32(float x) {
    uint32_t r;
    asm("cvt.rna.tf32.f32 %0, %1;" : "=r"(r) : "f"(x));
    return r;
}

__device__ __forceinline__ void mma_tf32(float c[4], const uint32_t a[4], const uint32_t b[2]) {
    asm volatile(
        "mma.sync.aligned.m16n8k8.row.col.f32.tf32.tf32.f32 "
        "{%0,%1,%2,%3}, {%4,%5,%6,%7}, {%8,%9}, {%0,%1,%2,%3};"
        : "+f"(c[0]), "+f"(c[1]), "+f"(c[2]), "+f"(c[3])
        : "r"(a[0]), "r"(a[1]), "r"(a[2]), "r"(a[3]), "r"(b[0]), "r"(b[1]));
}

__device__ __forceinline__ void cp_async16(uint32_t smem_addr, const void* gptr) {
    asm volatile("cp.async.cg.shared.global [%0], [%1], 16;\n"
                 :: "r"(smem_addr), "l"(gptr));
}
__device__ __forceinline__ void cp_commit() {
    asm volatile("cp.async.commit_group;\n" ::: "memory");
}
template<int N>
__device__ __forceinline__ void cp_wait() {
    asm volatile("cp.async.wait_group %0;\n" :: "n"(N) : "memory");
}

// ---------------- TF32 tensor-core GEMM, cp.async 3-stage pipeline ------------
// C[M,N] = A[M,K] @ W[N,K]^T + bias, then optionally gelu (FFN1) or fused
// residual+LayerNorm (out-proj / FFN2; requires grid.x == 1, N == 128).
// CTA tile 128x128, K chunk 32, 128 threads = 4 warps (2 on M x 2 on N),
// warp tile 64x64 (4 m16 x 8 n8, acc=128 regs). The warp tile sets the smem
// crossbar intensity: 16 LDS.64 per 32 mma = 8 MAC/byte, at the 128B/cyc
// crossbar break-even. ~254 regs * 128 thr * 2 CTAs = the register file, and
// 3 stages x 32KB x 2 CTAs = 192KB smem -> 2 CTAs/SM (round 8's 256-thread
// variant had 1 CTA/SM and nothing to overlap its barrier stalls with).
// GMEM->SMEM via cp.async.cg (raw fp32; mma.tf32 HW-truncates mantissa).
// k-slot remap (mma slot tg <-> physical k=2*tg) keeps every fragment operand
// pair a single LDS.64. 16B-block XOR swizzle per 32-word row.
#define STAGE_WORDS 8192   // (128 + 128) * 32
#define GEMM_SMEM_BYTES (3 * STAGE_WORDS * 4)   // 98304

template<int KDIM, bool DOGELU, bool FUSELN>
__global__ __launch_bounds__(128, 2) void gemm_tf32(
    const float* __restrict__ A, const float* __restrict__ W,
    const float* __restrict__ bias, float* __restrict__ C, int N,
    const float* __restrict__ Xres, const float* __restrict__ gamma,
    const float* __restrict__ beta) {
    extern __shared__ uint32_t sm[];

    const int tid  = threadIdx.x;
    const int warp = tid >> 5, lane = tid & 31;
    const int wm = warp & 1, wn = warp >> 1;     // 2 warps on M, 2 on N
    const int g  = lane >> 2, tg = lane & 3;
    const int m0 = blockIdx.y << 7;
    const int n0 = blockIdx.x << 7;

    const int rr = tid >> 3;   // copy row base (0..15)
    const int bk = tid & 7;    // 16B block within 32-word row

    auto issue = [&](int c) {
        const int st = c % 3;
        const int k0 = c << 5;
        uint32_t baseA = (uint32_t)__cvta_generic_to_shared(&sm[st * STAGE_WORDS]);
        uint32_t baseW = baseA + 4096 * 4;
#pragma unroll
        for (int i = 0; i < 8; i++) {
            int r = rr + (i << 4);
            uint32_t off = ((r << 5) + ((bk ^ (r & 7)) << 2)) << 2;
            cp_async16(baseA + off, &A[(size_t)(m0 + r) * KDIM + k0 + (bk << 2)]);
            cp_async16(baseW + off, &W[(size_t)(n0 + r) * KDIM + k0 + (bk << 2)]);
        }
        cp_commit();
    };

    float acc[4][8][4] = {};

    const int NC = KDIM / 32;
    issue(0);
    if (NC > 1) issue(1);

    for (int c = 0; c < NC; c++) {
        if (c == NC - 1) cp_wait<0>(); else cp_wait<1>();
        __syncthreads();
        if (c + 2 < NC) issue(c + 2);

        const uint32_t* As  = &sm[(c % 3) * STAGE_WORDS];
        const uint32_t* Ws_ = As + 4096;
#pragma unroll
        for (int ks = 0; ks < 4; ks++) {
            const int colw = (((2 * ks + (tg >> 1)) ^ g) << 2) + ((tg & 1) << 1);
            uint32_t afr[4][4];
#pragma unroll
            for (int mt = 0; mt < 4; mt++) {
                int r = (wm << 6) + (mt << 4) + g;
                uint2 p0 = *(const uint2*)&As[(r << 5) + colw];
                uint2 p1 = *(const uint2*)&As[((r + 8) << 5) + colw];
                afr[mt][0] = p0.x; afr[mt][1] = p1.x;
                afr[mt][2] = p0.y; afr[mt][3] = p1.y;
            }
#pragma unroll
            for (int nt = 0; nt < 8; nt++) {
                int rb = (wn << 6) + (nt << 3) + g;
                uint2 pb = *(const uint2*)&Ws_[(rb << 5) + colw];
                uint32_t bfr[2] = {pb.x, pb.y};
#pragma unroll
                for (int mt = 0; mt < 4; mt++)
                    mma_tf32(acc[mt][nt], afr[mt], bfr);
            }
        }
    }

    if (!FUSELN) {
#pragma unroll
        for (int mt = 0; mt < 4; mt++) {
            int row0 = m0 + (wm << 6) + (mt << 4) + g;
#pragma unroll
            for (int nt = 0; nt < 8; nt++) {
                int col = n0 + (wn << 6) + (nt << 3) + (tg << 1);
                float b0 = __ldg(&bias[col]);
                float b1 = __ldg(&bias[col + 1]);
                float v00 = acc[mt][nt][0] + b0, v01 = acc[mt][nt][1] + b1;
                float v10 = acc[mt][nt][2] + b0, v11 = acc[mt][nt][3] + b1;
                if (DOGELU) {
                    v00 = gelu_tanh(v00); v01 = gelu_tanh(v01);
                    v10 = gelu_tanh(v10); v11 = gelu_tanh(v11);
                }
                *(float2*)&C[(size_t)row0 * N + col]       = make_float2(v00, v01);
                *(float2*)&C[(size_t)(row0 + 8) * N + col] = make_float2(v10, v11);
            }
        }
    } else {
        // fused residual + LayerNorm over the full 128-col row (n0 == 0).
        // v = acc + bias + Xres computed IN PLACE in acc; LN(v)*gamma+beta -> C.
        __syncthreads();                      // all warps done with smem stages
        float* red = (float*)sm;              // [128 rows][2 wn][{sum,ss}]

        float psum[4][2], pss[4][2];
#pragma unroll
        for (int mt = 0; mt < 4; mt++)
#pragma unroll
            for (int rh = 0; rh < 2; rh++) {
                int row = m0 + (wm << 6) + (mt << 4) + (rh << 3) + g;
                const float* xr = Xres + (size_t)row * 128;
                float s = 0.f, ss = 0.f;
#pragma unroll
                for (int nt = 0; nt < 8; nt++) {
                    int col = (wn << 6) + (nt << 3) + (tg << 1);
                    float2 xv = *(const float2*)&xr[col];
                    float b0 = __ldg(&bias[col]);
                    float b1 = __ldg(&bias[col + 1]);
                    float v0 = acc[mt][nt][rh * 2 + 0] + b0 + xv.x;
                    float v1 = acc[mt][nt][rh * 2 + 1] + b1 + xv.y;
                    acc[mt][nt][rh * 2 + 0] = v0;
                    acc[mt][nt][rh * 2 + 1] = v1;
                    s  += v0 + v1;
                    ss += v0 * v0 + v1 * v1;
                }
                s  += __shfl_xor_sync(0xffffffffu, s, 1);
                s  += __shfl_xor_sync(0xffffffffu, s, 2);
                ss += __shfl_xor_sync(0xffffffffu, ss, 1);
                ss += __shfl_xor_sync(0xffffffffu, ss, 2);
                psum[mt][rh] = s;
                pss[mt][rh]  = ss;
            }
#pragma unroll
        for (int mt = 0; mt < 4; mt++)
#pragma unroll
            for (int rh = 0; rh < 2; rh++) {
                int rl = (wm << 6) + (mt << 4) + (rh << 3) + g;
                if (tg == 0) {
                    red[rl * 4 + wn * 2 + 0] = psum[mt][rh];
                    red[rl * 4 + wn * 2 + 1] = pss[mt][rh];
                }
            }
        __syncthreads();
#pragma unroll
        for (int mt = 0; mt < 4; mt++)
#pragma unroll
            for (int rh = 0; rh < 2; rh++) {
                int rl  = (wm << 6) + (mt << 4) + (rh << 3) + g;
                float s  = red[rl * 4 + 0] + red[rl * 4 + 2];
                float ss = red[rl * 4 + 1] + red[rl * 4 + 3];
                float mean = s * (1.0f / 128.0f);
                float var  = ss * (1.0f / 128.0f) - mean * mean;
                float rstd = rsqrtf(var + 1e-5f);
                float* op = C + (size_t)(m0 + rl) * 128;
#pragma unroll
                for (int nt = 0; nt < 8; nt++) {
                    int col = (wn << 6) + (nt << 3) + (tg << 1);
                    float g0 = __ldg(&gamma[col]),     b0 = __ldg(&beta[col]);
                    float g1 = __ldg(&gamma[col + 1]), b1 = __ldg(&beta[col + 1]);
                    float o0 = (acc[mt][nt][rh * 2 + 0] - mean) * rstd * g0 + b0;
                    float o1 = (acc[mt][nt][rh * 2 + 1] - mean) * rstd * g1 + b1;
                    *(float2*)&op[col] = make_float2(o0, o1);
                }
            }
    }
}

// ---------------- temporal attention (seqlen T=12) ---------------------------
__global__ __launch_bounds__(96) void temporal_attn(
    const float* __restrict__ QKV, float* __restrict__ Out) {
    __shared__ float s[TT * 384];
    int n = blockIdx.x;
    int b = blockIdx.y;
    for (int idx = threadIdx.x; idx < TT * 384; idx += 96) {
        int t = idx / 384, c = idx % 384;
        s[idx] = QKV[((size_t)(b * TT + t) * NS + n) * 384 + c];
    }
    __syncthreads();

    int h = threadIdx.x / TT;
    int q = threadIdx.x % TT;

    float qr[16];
#pragma unroll
    for (int d = 0; d < 16; d++) qr[d] = s[q * 384 + h * 16 + d];

    float sc[TT];
    float mx = -1e30f;
#pragma unroll
    for (int t2 = 0; t2 < TT; t2++) {
        const float* kr = &s[t2 * 384 + 128 + h * 16];
        float dot = 0.f;
#pragma unroll
        for (int d = 0; d < 16; d++) dot += qr[d] * kr[d];
        sc[t2] = dot * 0.25f;
        mx = fmaxf(mx, sc[t2]);
    }
    float l = 0.f;
#pragma unroll
    for (int t2 = 0; t2 < TT; t2++) {
        sc[t2] = __expf(sc[t2] - mx);
        l += sc[t2];
    }
    float acc[16] = {};
#pragma unroll
    for (int t2 = 0; t2 < TT; t2++) {
        float p = sc[t2];
        const float* vr = &s[t2 * 384 + 256 + h * 16];
#pragma unroll
        for (int d = 0; d < 16; d++) acc[d] += p * vr[d];
    }
    float inv = 1.f / l;
    float* op = &Out[((size_t)(b * TT + q) * NS + n) * 128 + h * 16];
#pragma unroll
    for (int d = 0; d < 16; d++) op[d] = acc[d] * inv;
}

// ---------------- spatial attention via tensor cores -------------------------
__global__ __launch_bounds__(128) void spatial_attn_mma(
    const float* __restrict__ QKV, const float* __restrict__ Bias,
    float* __restrict__ Out) {
    __shared__ uint32_t Ks [328 * 20];
    __shared__ uint32_t Vst[16 * 332];
    const int h  = blockIdx.x;
    const int bt = blockIdx.y;
    const size_t base = (size_t)bt * NS;
    const int tid = threadIdx.x;

    for (int idx = tid; idx < 328 * 16; idx += 128) {
        int key = idx >> 4, d = idx & 15;
        float kv = 0.f, vv = 0.f;
        if (key < NS) {
            const float* p = QKV + (base + key) * 384 + h * 16 + d;
            kv = p[128];
            vv = p[256];
        }
        Ks [key * 20 + d]   = f2tf32(kv);
        Vst[d * 332 + key]  = f2tf32(vv);
    }
    __syncthreads();

    const int warp = tid >> 5, lane = tid & 31;
    const int g = lane >> 2, tg = lane & 3;

    for (int qt = 0; qt < 6; qt++) {
        const int q0 = qt * 64 + warp * 16;
        if (q0 >= NS) break;

        const float* Qp0 = QKV + (base + q0 + g) * 384 + h * 16;
        const float* Qp1 = Qp0 + 8 * 384;
        float2 q00 = *(const float2*)(Qp0 + 2 * tg);
        float2 q01 = *(const float2*)(Qp0 + 8 + 2 * tg);
        float2 q10 = *(const float2*)(Qp1 + 2 * tg);
        float2 q11 = *(const float2*)(Qp1 + 8 + 2 * tg);
        uint32_t qa0[4] = {f2tf32(q00.x), f2tf32(q10.x), f2tf32(q00.y), f2tf32(q10.y)};
        uint32_t qa1[4] = {f2tf32(q01.x), f2tf32(q11.x), f2tf32(q01.y), f2tf32(q11.y)};

        const int qr0 = min(q0 + g, NS - 1);
        const int qr1 = min(q0 + g + 8, NS - 1);
        const float* brow0 = Bias + (size_t)qr0 * NS;
        const float* brow1 = Bias + (size_t)qr1 * NS;

        float o0[4] = {0.f, 0.f, 0.f, 0.f};
        float o1[4] = {0.f, 0.f, 0.f, 0.f};
        float l0 = 0.f, l1 = 0.f;

        for (int nt = 0; nt < 40; nt++) {
            const int k0 = nt * 8;
            float c[4] = {0.f, 0.f, 0.f, 0.f};
            {
                uint2 b = *(const uint2*)&Ks[(k0 + g) * 20 + 2 * tg];
                uint32_t bf[2] = {b.x, b.y};
                mma_tf32(c, qa0, bf);
            }
            {
                uint2 b = *(const uint2*)&Ks[(k0 + g) * 20 + 8 + 2 * tg];
                uint32_t bf[2] = {b.x, b.y};
                mma_tf32(c, qa1, bf);
            }
            const int col0 = k0 + 2 * tg;
            float p0 = __expf(c[0] * 0.25f + __ldg(brow0 + col0));
            float p1 = __expf(c[1] * 0.25f + __ldg(brow0 + col0 + 1));
            float p2 = __expf(c[2] * 0.25f + __ldg(brow1 + col0));
            float p3 = __expf(c[3] * 0.25f + __ldg(brow1 + col0 + 1));
            l0 += p0 + p1;
            l1 += p2 + p3;
            uint32_t pa[4] = {f2tf32(p0), f2tf32(p2), f2tf32(p1), f2tf32(p3)};
            {
                uint2 vb = *(const uint2*)&Vst[g * 332 + col0];
                uint32_t bf[2] = {vb.x, vb.y};
                mma_tf32(o0, pa, bf);
            }
            {
                uint2 vb = *(const uint2*)&Vst[(8 + g) * 332 + col0];
                uint32_t bf[2] = {vb.x, vb.y};
                mma_tf32(o1, pa, bf);
            }
        }
        {
            const int k0 = 320;
            float c[4] = {0.f, 0.f, 0.f, 0.f};
            {
                uint2 b = *(const uint2*)&Ks[(k0 + g) * 20 + 2 * tg];
                uint32_t bf[2] = {b.x, b.y};
                mma_tf32(c, qa0, bf);
            }
            {
                uint2 b = *(const uint2*)&Ks[(k0 + g) * 20 + 8 + 2 * tg];
                uint32_t bf[2] = {b.x, b.y};
                mma_tf32(c, qa1, bf);
            }
            const int col0 = k0 + 2 * tg;
            const int col1 = col0 + 1;
            float p0 = (col0 < NS) ? __expf(c[0] * 0.25f + __ldg(brow0 + col0)) : 0.f;
            float p1 = (col1 < NS) ? __expf(c[1] * 0.25f + __ldg(brow0 + col1)) : 0.f;
            float p2 = (col0 < NS) ? __expf(c[2] * 0.25f + __ldg(brow1 + col0)) : 0.f;
            float p3 = (col1 < NS) ? __expf(c[3] * 0.25f + __ldg(brow1 + col1)) : 0.f;
            l0 += p0 + p1;
            l1 += p2 + p3;
            uint32_t pa[4] = {f2tf32(p0), f2tf32(p2), f2tf32(p1), f2tf32(p3)};
            {
                uint2 vb = *(const uint2*)&Vst[g * 332 + col0];
                uint32_t bf[2] = {vb.x, vb.y};
                mma_tf32(o0, pa, bf);
            }
            {
                uint2 vb = *(const uint2*)&Vst[(8 + g) * 332 + col0];
                uint32_t bf[2] = {vb.x, vb.y};
                mma_tf32(o1, pa, bf);
            }
        }

        l0 += __shfl_xor_sync(0xffffffffu, l0, 1);
        l0 += __shfl_xor_sync(0xffffffffu, l0, 2);
        l1 += __shfl_xor_sync(0xffffffffu, l1, 1);
        l1 += __shfl_xor_sync(0xffffffffu, l1, 2);
        float inv0 = 1.f / l0;
        float inv1 = 1.f / l1;

        if (q0 + g < NS) {
            float* op = Out + (base + q0 + g) * 128 + h * 16;
            *(float2*)(op + 2 * tg)     = make_float2(o0[0] * inv0, o0[1] * inv0);
            *(float2*)(op + 8 + 2 * tg) = make_float2(o1[0] * inv0, o1[1] * inv0);
        }
        if (q0 + g + 8 < NS) {
            float* op = Out + (base + q0 + g + 8) * 128 + h * 16;
            *(float2*)(op + 2 * tg)     = make_float2(o0[2] * inv1, o0[3] * inv1);
            *(float2*)(op + 8 + 2 * tg) = make_float2(o1[2] * inv1, o1[3] * inv1);
        }
    }
}

// ---------------- driver ------------------------------------------------------
extern "C" void kernel_launch(void* const* d_in, const int* in_sizes, int n_in,
                              void* d_out, int out_size) {
    const float* x        = (const float*)d_in[0];
    const float* t_w_in   = (const float*)d_in[1];
    const float* t_b_in   = (const float*)d_in[2];
    const float* t_w_out  = (const float*)d_in[3];
    const float* t_b_out  = (const float*)d_in[4];
    const float* s_w_in   = (const float*)d_in[5];
    const float* s_b_in   = (const float*)d_in[6];
    const float* s_w_out  = (const float*)d_in[7];
    const float* s_b_out  = (const float*)d_in[8];
    const float* g_bias   = (const float*)d_in[9];
    const float* norm_t_g = (const float*)d_in[10];
    const float* norm_t_b = (const float*)d_in[11];
    const float* norm_s_g = (const float*)d_in[12];
    const float* norm_s_b = (const float*)d_in[13];
    const float* ff_w1    = (const float*)d_in[14];
    const float* ff_b1    = (const float*)d_in[15];
    const float* ff_w2    = (const float*)d_in[16];
    const float* ff_b2    = (const float*)d_in[17];
    const float* norm_f_g = (const float*)d_in[18];
    const float* norm_f_b = (const float*)d_in[19];
    float* out = (float*)d_out;

    float *buf, *attn, *x1, *x2;
    cudaGetSymbolAddress((void**)&buf,  g_buf);
    cudaGetSymbolAddress((void**)&attn, g_attn);
    cudaGetSymbolAddress((void**)&x1,   g_x1);
    cudaGetSymbolAddress((void**)&x2,   g_x2);

    cudaFuncSetAttribute(gemm_tf32<128, false, false>, cudaFuncAttributeMaxDynamicSharedMemorySize, GEMM_SMEM_BYTES);
    cudaFuncSetAttribute(gemm_tf32<128, false, true >, cudaFuncAttributeMaxDynamicSharedMemorySize, GEMM_SMEM_BYTES);
    cudaFuncSetAttribute(gemm_tf32<128, true,  false>, cudaFuncAttributeMaxDynamicSharedMemorySize, GEMM_SMEM_BYTES);
    cudaFuncSetAttribute(gemm_tf32<512, false, true >, cudaFuncAttributeMaxDynamicSharedMemorySize, GEMM_SMEM_BYTES);

    const int MB = MTOK / 128;   // 975

    // --- temporal block ---
    gemm_tf32<128, false, false><<<dim3(3, MB), 128, GEMM_SMEM_BYTES>>>(
        x, t_w_in, t_b_in, buf, 384, nullptr, nullptr, nullptr);
    temporal_attn<<<dim3(NS, BB), 96>>>(buf, attn);
    gemm_tf32<128, false, true><<<dim3(1, MB), 128, GEMM_SMEM_BYTES>>>(
        attn, t_w_out, t_b_out, x1, 128, x, norm_t_g, norm_t_b);

    // --- spatial block ---
    gemm_tf32<128, false, false><<<dim3(3, MB), 128, GEMM_SMEM_BYTES>>>(
        x1, s_w_in, s_b_in, buf, 384, nullptr, nullptr, nullptr);
    spatial_attn_mma<<<dim3(8, BB * TT), 128>>>(buf, g_bias, attn);
    gemm_tf32<128, false, true><<<dim3(1, MB), 128, GEMM_SMEM_BYTES>>>(
        attn, s_w_out, s_b_out, x2, 128, x1, norm_s_g, norm_s_b);

    // --- FFN ---
    gemm_tf32<128, true, false><<<dim3(4, MB), 128, GEMM_SMEM_BYTES>>>(
        x2, ff_w1, ff_b1, buf, 512, nullptr, nullptr, nullptr);
    gemm_tf32<512, false, true><<<dim3(1, MB), 128, GEMM_SMEM_BYTES>>>(
        buf, ff_w2, ff_b2, out, 128, x2, norm_f_g, norm_f_b);
}

// round 14
// speedup vs baseline: 1.2314x; 1.0920x over previous
#include <cuda_runtime.h>
#include <math.h>
#include <stdint.h>

// Problem constants
#define BB 32
#define TT 12
#define NS 325
#define DD 128
#define FF 512
#define MTOK (BB*TT*NS)   // 124800 tokens = 975 * 128 exactly

// ---------------- scratch (static device allocations; no runtime alloc) ------
__device__ float g_buf  [(size_t)MTOK * 512];
__device__ float g_attn [(size_t)MTOK * 128];
__device__ float g_x1   [(size_t)MTOK * 128];
__device__ float g_x2   [(size_t)MTOK * 128];

// ---------------- helpers ----------------------------------------------------
__device__ __forceinline__ float gelu_tanh(float x) {
    float x3 = x * x * x;
    float t  = tanhf(0.7978845608028654f * (x + 0.044715f * x3));
    return 0.5f * x * (1.0f + t);
}

__device__ __forceinline__ uint32_t f2tf32(float x) {
    uint32_t r;
    asm("cvt.rna.tf32.f32 %0, %1;" : "=r"(r) : "f"(x));
    return r;
}

// pack two fp32 bit-patterns (lo = even k, hi = odd k) into one f16x2 register.
// cvt.rn.f16x2.f32 d, a, b  ->  d = { hi = a, lo = b }
__device__ __forceinline__ uint32_t pack_f16x2(uint32_t lo, uint32_t hi) {
    uint32_t r;
    asm("cvt.rn.f16x2.f32 %0, %1, %2;"
        : "=r"(r) : "f"(__uint_as_float(hi)), "f"(__uint_as_float(lo)));
    return r;
}

__device__ __forceinline__ void mma_tf32(float c[4], const uint32_t a[4], const uint32_t b[2]) {
    asm volatile(
        "mma.sync.aligned.m16n8k8.row.col.f32.tf32.tf32.f32 "
        "{%0,%1,%2,%3}, {%4,%5,%6,%7}, {%8,%9}, {%0,%1,%2,%3};"
        : "+f"(c[0]), "+f"(c[1]), "+f"(c[2]), "+f"(c[3])
        : "r"(a[0]), "r"(a[1]), "r"(a[2]), "r"(a[3]), "r"(b[0]), "r"(b[1]));
}

__device__ __forceinline__ void mma_f16(float c[4], const uint32_t a[4], const uint32_t b[2]) {
    asm volatile(
        "mma.sync.aligned.m16n8k16.row.col.f32.f16.f16.f32 "
        "{%0,%1,%2,%3}, {%4,%5,%6,%7}, {%8,%9}, {%0,%1,%2,%3};"
        : "+f"(c[0]), "+f"(c[1]), "+f"(c[2]), "+f"(c[3])
        : "r"(a[0]), "r"(a[1]), "r"(a[2]), "r"(a[3]), "r"(b[0]), "r"(b[1]));
}

__device__ __forceinline__ void cp_async16(uint32_t smem_addr, const void* gptr) {
    asm volatile("cp.async.cg.shared.global [%0], [%1], 16;\n"
                 :: "r"(smem_addr), "l"(gptr));
}
__device__ __forceinline__ void cp_commit() {
    asm volatile("cp.async.commit_group;\n" ::: "memory");
}
template<int N>
__device__ __forceinline__ void cp_wait() {
    asm volatile("cp.async.wait_group %0;\n" :: "n"(N) : "memory");
}

// ---------------- FP16 tensor-core GEMM, cp.async 3-stage pipeline ------------
// C[M,N] = A[M,K] @ W[N,K]^T + bias, then optionally gelu (FFN1) or fused
// residual+LayerNorm (out-proj / FFN2; requires grid.x == 1, N == 128).
// CTA tile 128x128, K chunk 32, 128 threads = 4 warps (2 on M x 2 on N),
// warp tile 64x64. Inner math: mma.m16n8k16 f16 (fp32 accumulate) — K=16 per
// instruction halves the HMMA count vs tf32 k8, which round-10 profiling
// showed to be the binding pipe. fp16 keeps tf32's 10-bit mantissa; inputs
// are O(1) so range is safe; cvt.rn rounds (better than the old raw-RZ).
// GMEM->SMEM stays cp.async fp32 (3 stages x 32KB -> 2 CTAs/SM); fragments
// load as LDS.64 fp32 pairs (consecutive k) and pack to f16x2 in registers.
// 16B-block XOR swizzle per 32-word row.
#define STAGE_WORDS 8192   // (128 + 128) * 32
#define GEMM_SMEM_BYTES (3 * STAGE_WORDS * 4)   // 98304

template<int KDIM, bool DOGELU, bool FUSELN>
__global__ __launch_bounds__(128, 2) void gemm_f16(
    const float* __restrict__ A, const float* __restrict__ W,
    const float* __restrict__ bias, float* __restrict__ C, int N,
    const float* __restrict__ Xres, const float* __restrict__ gamma,
    const float* __restrict__ beta) {
    extern __shared__ uint32_t sm[];

    const int tid  = threadIdx.x;
    const int warp = tid >> 5, lane = tid & 31;
    const int wm = warp & 1, wn = warp >> 1;     // 2 warps on M, 2 on N
    const int g  = lane >> 2, tg = lane & 3;
    const int m0 = blockIdx.y << 7;
    const int n0 = blockIdx.x << 7;

    const int rr = tid >> 3;   // copy row base (0..15)
    const int bk = tid & 7;    // 16B block within 32-word row

    auto issue = [&](int c) {
        const int st = c % 3;
        const int k0 = c << 5;
        uint32_t baseA = (uint32_t)__cvta_generic_to_shared(&sm[st * STAGE_WORDS]);
        uint32_t baseW = baseA + 4096 * 4;
#pragma unroll
        for (int i = 0; i < 8; i++) {
            int r = rr + (i << 4);
            uint32_t off = ((r << 5) + ((bk ^ (r & 7)) << 2)) << 2;
            cp_async16(baseA + off, &A[(size_t)(m0 + r) * KDIM + k0 + (bk << 2)]);
            cp_async16(baseW + off, &W[(size_t)(n0 + r) * KDIM + k0 + (bk << 2)]);
        }
        cp_commit();
    };

    float acc[4][8][4] = {};

    const int NC = KDIM / 32;
    issue(0);
    if (NC > 1) issue(1);

    for (int c = 0; c < NC; c++) {
        if (c == NC - 1) cp_wait<0>(); else cp_wait<1>();
        __syncthreads();
        if (c + 2 < NC) issue(c + 2);

        const uint32_t* As  = &sm[(c % 3) * STAGE_WORDS];
        const uint32_t* Ws_ = As + 4096;
        // two k16 steps per 32-K chunk
#pragma unroll
        for (int ks2 = 0; ks2 < 2; ks2++) {
            // word offsets of this thread's two k-pairs (even k first):
            //   pair A: k = ks2*16 + 2tg      -> 4-word block (ks2*4 + tg/2)
            //   pair B: k = ks2*16 + 8 + 2tg  -> 4-word block (ks2*4 + 2 + tg/2)
            const int cwA = ((((ks2 << 2) + (tg >> 1)) ^ g) << 2) + ((tg & 1) << 1);
            const int cwB = ((((ks2 << 2) + 2 + (tg >> 1)) ^ g) << 2) + ((tg & 1) << 1);
            uint32_t afr[4][4];
#pragma unroll
            for (int mt = 0; mt < 4; mt++) {
                int r0 = (wm << 6) + (mt << 4) + g;
                uint2 pa0 = *(const uint2*)&As[(r0 << 5) + cwA];
                uint2 pa1 = *(const uint2*)&As[((r0 + 8) << 5) + cwA];
                uint2 pa2 = *(const uint2*)&As[(r0 << 5) + cwB];
                uint2 pa3 = *(const uint2*)&As[((r0 + 8) << 5) + cwB];
                afr[mt][0] = pack_f16x2(pa0.x, pa0.y);
                afr[mt][1] = pack_f16x2(pa1.x, pa1.y);
                afr[mt][2] = pack_f16x2(pa2.x, pa2.y);
                afr[mt][3] = pack_f16x2(pa3.x, pa3.y);
            }
#pragma unroll
            for (int nt = 0; nt < 8; nt++) {
                int rb = (wn << 6) + (nt << 3) + g;
                uint2 pb0 = *(const uint2*)&Ws_[(rb << 5) + cwA];
                uint2 pb1 = *(const uint2*)&Ws_[(rb << 5) + cwB];
                uint32_t bfr[2] = {pack_f16x2(pb0.x, pb0.y), pack_f16x2(pb1.x, pb1.y)};
#pragma unroll
                for (int mt = 0; mt < 4; mt++)
                    mma_f16(acc[mt][nt], afr[mt], bfr);
            }
        }
    }

    if (!FUSELN) {
#pragma unroll
        for (int mt = 0; mt < 4; mt++) {
            int row0 = m0 + (wm << 6) + (mt << 4) + g;
#pragma unroll
            for (int nt = 0; nt < 8; nt++) {
                int col = n0 + (wn << 6) + (nt << 3) + (tg << 1);
                float b0 = __ldg(&bias[col]);
                float b1 = __ldg(&bias[col + 1]);
                float v00 = acc[mt][nt][0] + b0, v01 = acc[mt][nt][1] + b1;
                float v10 = acc[mt][nt][2] + b0, v11 = acc[mt][nt][3] + b1;
                if (DOGELU) {
                    v00 = gelu_tanh(v00); v01 = gelu_tanh(v01);
                    v10 = gelu_tanh(v10); v11 = gelu_tanh(v11);
                }
                *(float2*)&C[(size_t)row0 * N + col]       = make_float2(v00, v01);
                *(float2*)&C[(size_t)(row0 + 8) * N + col] = make_float2(v10, v11);
            }
        }
    } else {
        // fused residual + LayerNorm over the full 128-col row (n0 == 0).
        __syncthreads();                      // all warps done with smem stages
        float* red = (float*)sm;              // [128 rows][2 wn][{sum,ss}]

        float psum[4][2], pss[4][2];
#pragma unroll
        for (int mt = 0; mt < 4; mt++)
#pragma unroll
            for (int rh = 0; rh < 2; rh++) {
                int row = m0 + (wm << 6) + (mt << 4) + (rh << 3) + g;
                const float* xr = Xres + (size_t)row * 128;
                float s = 0.f, ss = 0.f;
#pragma unroll
                for (int nt = 0; nt < 8; nt++) {
                    int col = (wn << 6) + (nt << 3) + (tg << 1);
                    float2 xv = *(const float2*)&xr[col];
                    float b0 = __ldg(&bias[col]);
                    float b1 = __ldg(&bias[col + 1]);
                    float v0 = acc[mt][nt][rh * 2 + 0] + b0 + xv.x;
                    float v1 = acc[mt][nt][rh * 2 + 1] + b1 + xv.y;
                    acc[mt][nt][rh * 2 + 0] = v0;
                    acc[mt][nt][rh * 2 + 1] = v1;
                    s  += v0 + v1;
                    ss += v0 * v0 + v1 * v1;
                }
                s  += __shfl_xor_sync(0xffffffffu, s, 1);
                s  += __shfl_xor_sync(0xffffffffu, s, 2);
                ss += __shfl_xor_sync(0xffffffffu, ss, 1);
                ss += __shfl_xor_sync(0xffffffffu, ss, 2);
                psum[mt][rh] = s;
                pss[mt][rh]  = ss;
            }
#pragma unroll
        for (int mt = 0; mt < 4; mt++)
#pragma unroll
            for (int rh = 0; rh < 2; rh++) {
                int rl = (wm << 6) + (mt << 4) + (rh << 3) + g;
                if (tg == 0) {
                    red[rl * 4 + wn * 2 + 0] = psum[mt][rh];
                    red[rl * 4 + wn * 2 + 1] = pss[mt][rh];
                }
            }
        __syncthreads();
#pragma unroll
        for (int mt = 0; mt < 4; mt++)
#pragma unroll
            for (int rh = 0; rh < 2; rh++) {
                int rl  = (wm << 6) + (mt << 4) + (rh << 3) + g;
                float s  = red[rl * 4 + 0] + red[rl * 4 + 2];
                float ss = red[rl * 4 + 1] + red[rl * 4 + 3];
                float mean = s * (1.0f / 128.0f);
                float var  = ss * (1.0f / 128.0f) - mean * mean;
                float rstd = rsqrtf(var + 1e-5f);
                float* op = C + (size_t)(m0 + rl) * 128;
#pragma unroll
                for (int nt = 0; nt < 8; nt++) {
                    int col = (wn << 6) + (nt << 3) + (tg << 1);
                    float g0 = __ldg(&gamma[col]),     b0 = __ldg(&beta[col]);
                    float g1 = __ldg(&gamma[col + 1]), b1 = __ldg(&beta[col + 1]);
                    float o0 = (acc[mt][nt][rh * 2 + 0] - mean) * rstd * g0 + b0;
                    float o1 = (acc[mt][nt][rh * 2 + 1] - mean) * rstd * g1 + b1;
                    *(float2*)&op[col] = make_float2(o0, o1);
                }
            }
    }
}

// ---------------- temporal attention (seqlen T=12) ---------------------------
__global__ __launch_bounds__(96) void temporal_attn(
    const float* __restrict__ QKV, float* __restrict__ Out) {
    __shared__ float s[TT * 384];
    int n = blockIdx.x;
    int b = blockIdx.y;
    for (int idx = threadIdx.x; idx < TT * 384; idx += 96) {
        int t = idx / 384, c = idx % 384;
        s[idx] = QKV[((size_t)(b * TT + t) * NS + n) * 384 + c];
    }
    __syncthreads();

    int h = threadIdx.x / TT;
    int q = threadIdx.x % TT;

    float qr[16];
#pragma unroll
    for (int d = 0; d < 16; d++) qr[d] = s[q * 384 + h * 16 + d];

    float sc[TT];
    float mx = -1e30f;
#pragma unroll
    for (int t2 = 0; t2 < TT; t2++) {
        const float* kr = &s[t2 * 384 + 128 + h * 16];
        float dot = 0.f;
#pragma unroll
        for (int d = 0; d < 16; d++) dot += qr[d] * kr[d];
        sc[t2] = dot * 0.25f;
        mx = fmaxf(mx, sc[t2]);
    }
    float l = 0.f;
#pragma unroll
    for (int t2 = 0; t2 < TT; t2++) {
        sc[t2] = __expf(sc[t2] - mx);
        l += sc[t2];
    }
    float acc[16] = {};
#pragma unroll
    for (int t2 = 0; t2 < TT; t2++) {
        float p = sc[t2];
        const float* vr = &s[t2 * 384 + 256 + h * 16];
#pragma unroll
        for (int d = 0; d < 16; d++) acc[d] += p * vr[d];
    }
    float inv = 1.f / l;
    float* op = &Out[((size_t)(b * TT + q) * NS + n) * 128 + h * 16];
#pragma unroll
    for (int d = 0; d < 16; d++) op[d] = acc[d] * inv;
}

// ---------------- spatial attention via tensor cores (tf32, unchanged) -------
__global__ __launch_bounds__(128) void spatial_attn_mma(
    const float* __restrict__ QKV, const float* __restrict__ Bias,
    float* __restrict__ Out) {
    __shared__ uint32_t Ks [328 * 20];
    __shared__ uint32_t Vst[16 * 332];
    const int h  = blockIdx.x;
    const int bt = blockIdx.y;
    const size_t base = (size_t)bt * NS;
    const int tid = threadIdx.x;

    for (int idx = tid; idx < 328 * 16; idx += 128) {
        int key = idx >> 4, d = idx & 15;
        float kv = 0.f, vv = 0.f;
        if (key < NS) {
            const float* p = QKV + (base + key) * 384 + h * 16 + d;
            kv = p[128];
            vv = p[256];
        }
        Ks [key * 20 + d]   = f2tf32(kv);
        Vst[d * 332 + key]  = f2tf32(vv);
    }
    __syncthreads();

    const int warp = tid >> 5, lane = tid & 31;
    const int g = lane >> 2, tg = lane & 3;

    for (int qt = 0; qt < 6; qt++) {
        const int q0 = qt * 64 + warp * 16;
        if (q0 >= NS) break;

        const float* Qp0 = QKV + (base + q0 + g) * 384 + h * 16;
        const float* Qp1 = Qp0 + 8 * 384;
        float2 q00 = *(const float2*)(Qp0 + 2 * tg);
        float2 q01 = *(const float2*)(Qp0 + 8 + 2 * tg);
        float2 q10 = *(const float2*)(Qp1 + 2 * tg);
        float2 q11 = *(const float2*)(Qp1 + 8 + 2 * tg);
        uint32_t qa0[4] = {f2tf32(q00.x), f2tf32(q10.x), f2tf32(q00.y), f2tf32(q10.y)};
        uint32_t qa1[4] = {f2tf32(q01.x), f2tf32(q11.x), f2tf32(q01.y), f2tf32(q11.y)};

        const int qr0 = min(q0 + g, NS - 1);
        const int qr1 = min(q0 + g + 8, NS - 1);
        const float* brow0 = Bias + (size_t)qr0 * NS;
        const float* brow1 = Bias + (size_t)qr1 * NS;

        float o0[4] = {0.f, 0.f, 0.f, 0.f};
        float o1[4] = {0.f, 0.f, 0.f, 0.f};
        float l0 = 0.f, l1 = 0.f;

        for (int nt = 0; nt < 40; nt++) {
            const int k0 = nt * 8;
            float c[4] = {0.f, 0.f, 0.f, 0.f};
            {
                uint2 b = *(const uint2*)&Ks[(k0 + g) * 20 + 2 * tg];
                uint32_t bf[2] = {b.x, b.y};
                mma_tf32(c, qa0, bf);
            }
            {
                uint2 b = *(const uint2*)&Ks[(k0 + g) * 20 + 8 + 2 * tg];
                uint32_t bf[2] = {b.x, b.y};
                mma_tf32(c, qa1, bf);
            }
            const int col0 = k0 + 2 * tg;
            float p0 = __expf(c[0] * 0.25f + __ldg(brow0 + col0));
            float p1 = __expf(c[1] * 0.25f + __ldg(brow0 + col0 + 1));
            float p2 = __expf(c[2] * 0.25f + __ldg(brow1 + col0));
            float p3 = __expf(c[3] * 0.25f + __ldg(brow1 + col0 + 1));
            l0 += p0 + p1;
            l1 += p2 + p3;
            uint32_t pa[4] = {f2tf32(p0), f2tf32(p2), f2tf32(p1), f2tf32(p3)};
            {
                uint2 vb = *(const uint2*)&Vst[g * 332 + col0];
                uint32_t bf[2] = {vb.x, vb.y};
                mma_tf32(o0, pa, bf);
            }
            {
                uint2 vb = *(const uint2*)&Vst[(8 + g) * 332 + col0];
                uint32_t bf[2] = {vb.x, vb.y};
                mma_tf32(o1, pa, bf);
            }
        }
        {
            const int k0 = 320;
            float c[4] = {0.f, 0.f, 0.f, 0.f};
            {
                uint2 b = *(const uint2*)&Ks[(k0 + g) * 20 + 2 * tg];
                uint32_t bf[2] = {b.x, b.y};
                mma_tf32(c, qa0, bf);
            }
            {
                uint2 b = *(const uint2*)&Ks[(k0 + g) * 20 + 8 + 2 * tg];
                uint32_t bf[2] = {b.x, b.y};
                mma_tf32(c, qa1, bf);
            }
            const int col0 = k0 + 2 * tg;
            const int col1 = col0 + 1;
            float p0 = (col0 < NS) ? __expf(c[0] * 0.25f + __ldg(brow0 + col0)) : 0.f;
            float p1 = (col1 < NS) ? __expf(c[1] * 0.25f + __ldg(brow0 + col1)) : 0.f;
            float p2 = (col0 < NS) ? __expf(c[2] * 0.25f + __ldg(brow1 + col0)) : 0.f;
            float p3 = (col1 < NS) ? __expf(c[3] * 0.25f + __ldg(brow1 + col1)) : 0.f;
            l0 += p0 + p1;
            l1 += p2 + p3;
            uint32_t pa[4] = {f2tf32(p0), f2tf32(p2), f2tf32(p1), f2tf32(p3)};
            {
                uint2 vb = *(const uint2*)&Vst[g * 332 + col0];
                uint32_t bf[2] = {vb.x, vb.y};
                mma_tf32(o0, pa, bf);
            }
            {
                uint2 vb = *(const uint2*)&Vst[(8 + g) * 332 + col0];
                uint32_t bf[2] = {vb.x, vb.y};
                mma_tf32(o1, pa, bf);
            }
        }

        l0 += __shfl_xor_sync(0xffffffffu, l0, 1);
        l0 += __shfl_xor_sync(0xffffffffu, l0, 2);
        l1 += __shfl_xor_sync(0xffffffffu, l1, 1);
        l1 += __shfl_xor_sync(0xffffffffu, l1, 2);
        float inv0 = 1.f / l0;
        float inv1 = 1.f / l1;

        if (q0 + g < NS) {
            float* op = Out + (base + q0 + g) * 128 + h * 16;
            *(float2*)(op + 2 * tg)     = make_float2(o0[0] * inv0, o0[1] * inv0);
            *(float2*)(op + 8 + 2 * tg) = make_float2(o1[0] * inv0, o1[1] * inv0);
        }
        if (q0 + g + 8 < NS) {
            float* op = Out + (base + q0 + g + 8) * 128 + h * 16;
            *(float2*)(op + 2 * tg)     = make_float2(o0[2] * inv1, o0[3] * inv1);
            *(float2*)(op + 8 + 2 * tg) = make_float2(o1[2] * inv1, o1[3] * inv1);
        }
    }
}

// ---------------- driver ------------------------------------------------------
extern "C" void kernel_launch(void* const* d_in, const int* in_sizes, int n_in,
                              void* d_out, int out_size) {
    const float* x        = (const float*)d_in[0];
    const float* t_w_in   = (const float*)d_in[1];
    const float* t_b_in   = (const float*)d_in[2];
    const float* t_w_out  = (const float*)d_in[3];
    const float* t_b_out  = (const float*)d_in[4];
    const float* s_w_in   = (const float*)d_in[5];
    const float* s_b_in   = (const float*)d_in[6];
    const float* s_w_out  = (const float*)d_in[7];
    const float* s_b_out  = (const float*)d_in[8];
    const float* g_bias   = (const float*)d_in[9];
    const float* norm_t_g = (const float*)d_in[10];
    const float* norm_t_b = (const float*)d_in[11];
    const float* norm_s_g = (const float*)d_in[12];
    const float* norm_s_b = (const float*)d_in[13];
    const float* ff_w1    = (const float*)d_in[14];
    const float* ff_b1    = (const float*)d_in[15];
    const float* ff_w2    = (const float*)d_in[16];
    const float* ff_b2    = (const float*)d_in[17];
    const float* norm_f_g = (const float*)d_in[18];
    const float* norm_f_b = (const float*)d_in[19];
    float* out = (float*)d_out;

    float *buf, *attn, *x1, *x2;
    cudaGetSymbolAddress((void**)&buf,  g_buf);
    cudaGetSymbolAddress((void**)&attn, g_attn);
    cudaGetSymbolAddress((void**)&x1,   g_x1);
    cudaGetSymbolAddress((void**)&x2,   g_x2);

    cudaFuncSetAttribute(gemm_f16<128, false, false>, cudaFuncAttributeMaxDynamicSharedMemorySize, GEMM_SMEM_BYTES);
    cudaFuncSetAttribute(gemm_f16<128, false, true >, cudaFuncAttributeMaxDynamicSharedMemorySize, GEMM_SMEM_BYTES);
    cudaFuncSetAttribute(gemm_f16<128, true,  false>, cudaFuncAttributeMaxDynamicSharedMemorySize, GEMM_SMEM_BYTES);
    cudaFuncSetAttribute(gemm_f16<512, false, true >, cudaFuncAttributeMaxDynamicSharedMemorySize, GEMM_SMEM_BYTES);

    const int MB = MTOK / 128;   // 975

    // --- temporal block ---
    gemm_f16<128, false, false><<<dim3(3, MB), 128, GEMM_SMEM_BYTES>>>(
        x, t_w_in, t_b_in, buf, 384, nullptr, nullptr, nullptr);
    temporal_attn<<<dim3(NS, BB), 96>>>(buf, attn);
    gemm_f16<128, false, true><<<dim3(1, MB), 128, GEMM_SMEM_BYTES>>>(
        attn, t_w_out, t_b_out, x1, 128, x, norm_t_g, norm_t_b);

    // --- spatial block ---
    gemm_f16<128, false, false><<<dim3(3, MB), 128, GEMM_SMEM_BYTES>>>(
        x1, s_w_in, s_b_in, buf, 384, nullptr, nullptr, nullptr);
    spatial_attn_mma<<<dim3(8, BB * TT), 128>>>(buf, g_bias, attn);
    gemm_f16<128, false, true><<<dim3(1, MB), 128, GEMM_SMEM_BYTES>>>(
        attn, s_w_out, s_b_out, x2, 128, x1, norm_s_g, norm_s_b);

    // --- FFN ---
    gemm_f16<128, true, false><<<dim3(4, MB), 128, GEMM_SMEM_BYTES>>>(
        x2, ff_w1, ff_b1, buf, 512, nullptr, nullptr, nullptr);
    gemm_f16<512, false, true><<<dim3(1, MB), 128, GEMM_SMEM_BYTES>>>(
        buf, ff_w2, ff_b2, out, 128, x2, norm_f_g, norm_f_b);
}

// round 15
// speedup vs baseline: 1.4226x; 1.1553x over previous
#include <cuda_runtime.h>
#include <cuda_fp16.h>
#include <math.h>
#include <stdint.h>

// Problem constants
#define BB 32
#define TT 12
#define NS 325
#define DD 128
#define FF 512
#define MTOK (BB*TT*NS)   // 124800 tokens = 975 * 128 exactly

// ---------------- scratch (static device allocations; no runtime alloc) ------
__device__ float  g_buf  [(size_t)MTOK * 384];   // QKV fp32 (attention input)
__device__ __half g_h16  [(size_t)MTOK * 512];   // FFN hidden, f16 only
__device__ __half g_attn16[(size_t)MTOK * 128];  // attention out, f16 only
__device__ float  g_x1   [(size_t)MTOK * 128];
__device__ __half g_x116 [(size_t)MTOK * 128];
__device__ float  g_x2   [(size_t)MTOK * 128];
__device__ __half g_x216 [(size_t)MTOK * 128];
__device__ __half g_x16  [(size_t)MTOK * 128];   // f16 copy of input x
__device__ __half g_w16  [262144];               // all 6 weight matrices, f16

// weight pool offsets (elements)
#define W_T_IN   0
#define W_T_OUT  49152
#define W_S_IN   65536
#define W_S_OUT  114688
#define W_FF1    131072
#define W_FF2    196608

// ---------------- helpers ----------------------------------------------------
__device__ __forceinline__ float gelu_tanh(float x) {
    float x3 = x * x * x;
    float t  = tanhf(0.7978845608028654f * (x + 0.044715f * x3));
    return 0.5f * x * (1.0f + t);
}

__device__ __forceinline__ uint32_t f2tf32(float x) {
    uint32_t r;
    asm("cvt.rna.tf32.f32 %0, %1;" : "=r"(r) : "f"(x));
    return r;
}

__device__ __forceinline__ void mma_tf32(float c[4], const uint32_t a[4], const uint32_t b[2]) {
    asm volatile(
        "mma.sync.aligned.m16n8k8.row.col.f32.tf32.tf32.f32 "
        "{%0,%1,%2,%3}, {%4,%5,%6,%7}, {%8,%9}, {%0,%1,%2,%3};"
        : "+f"(c[0]), "+f"(c[1]), "+f"(c[2]), "+f"(c[3])
        : "r"(a[0]), "r"(a[1]), "r"(a[2]), "r"(a[3]), "r"(b[0]), "r"(b[1]));
}

__device__ __forceinline__ void mma_f16(float c[4], const uint32_t a[4], const uint32_t b[2]) {
    asm volatile(
        "mma.sync.aligned.m16n8k16.row.col.f32.f16.f16.f32 "
        "{%0,%1,%2,%3}, {%4,%5,%6,%7}, {%8,%9}, {%0,%1,%2,%3};"
        : "+f"(c[0]), "+f"(c[1]), "+f"(c[2]), "+f"(c[3])
        : "r"(a[0]), "r"(a[1]), "r"(a[2]), "r"(a[3]), "r"(b[0]), "r"(b[1]));
}

__device__ __forceinline__ void cp_async16(uint32_t smem_addr, const void* gptr) {
    asm volatile("cp.async.cg.shared.global [%0], [%1], 16;\n"
                 :: "r"(smem_addr), "l"(gptr));
}
__device__ __forceinline__ void cp_commit() {
    asm volatile("cp.async.commit_group;\n" ::: "memory");
}
template<int N>
__device__ __forceinline__ void cp_wait() {
    asm volatile("cp.async.wait_group %0;\n" :: "n"(N) : "memory");
}

// ---------------- f32 -> f16 conversion (vectorized) -------------------------
__global__ void conv_f16(const float* __restrict__ in, __half* __restrict__ out, int n4) {
    int i = blockIdx.x * blockDim.x + threadIdx.x;
    if (i < n4) {
        float4 v = ((const float4*)in)[i];
        __half2 lo = __floats2half2_rn(v.x, v.y);
        __half2 hi = __floats2half2_rn(v.z, v.w);
        ((__half2*)out)[2 * i]     = lo;
        ((__half2*)out)[2 * i + 1] = hi;
    }
}

// ---------------- FP16-operand tensor-core GEMM, cp.async 3-stage ------------
// C[M,N] = A16[M,K] @ W16[N,K]^T + bias; optional gelu / fused residual+LN.
// A and W live in gmem as f16 (128B rows per 64-K chunk) -> cp.async moves
// HALF the bytes of round 14 and the inner loop has ZERO cvt: fragment loads
// are LDS.32 (one f16x2 mma register each), conflict-free under the 16B-block
// XOR swizzle (word = (blk^g)*4+tg covers all banks). K chunk 64, stage 32KB
// (128 A rows + 128 B rows), 3 stages = 96KB -> 2 CTAs/SM. 128 thr, 4 warps
// (2 M x 2 N), warp tile 64x64.
// OUT16: non-LN output stored as f16 (FFN1). FUSELN: fp32 out + optional f16
// copy (C16 != null) for the next GEMM's A operand.
#define STAGE_WORDS 8192   // (128 + 128) rows * 32 words
#define GEMM_SMEM_BYTES (3 * STAGE_WORDS * 4)   // 98304

template<int KDIM, bool DOGELU, bool FUSELN, bool OUT16>
__global__ __launch_bounds__(128, 2) void gemm_f16(
    const __half* __restrict__ A, const __half* __restrict__ W,
    const float* __restrict__ bias, void* __restrict__ Cout, int N,
    const float* __restrict__ Xres, const float* __restrict__ gamma,
    const float* __restrict__ beta, __half* __restrict__ C16) {
    extern __shared__ uint32_t sm[];

    const int tid  = threadIdx.x;
    const int warp = tid >> 5, lane = tid & 31;
    const int wm = warp & 1, wn = warp >> 1;     // 2 warps on M, 2 on N
    const int g  = lane >> 2, tg = lane & 3;
    const int m0 = blockIdx.y << 7;
    const int n0 = blockIdx.x << 7;

    const int rr = tid >> 3;   // copy row base (0..15)
    const int bk = tid & 7;    // 16B block within 128B row

    auto issue = [&](int c) {
        const int st = c % 3;
        const int k0 = c << 6;                   // 64 k per chunk
        uint32_t baseA = (uint32_t)__cvta_generic_to_shared(&sm[st * STAGE_WORDS]);
        uint32_t baseW = baseA + 4096 * 4;
#pragma unroll
        for (int i = 0; i < 8; i++) {
            int r = rr + (i << 4);
            uint32_t off = ((r << 5) + ((bk ^ (r & 7)) << 2)) << 2;
            cp_async16(baseA + off, &A[(size_t)(m0 + r) * KDIM + k0 + (bk << 3)]);
            cp_async16(baseW + off, &W[(size_t)(n0 + r) * KDIM + k0 + (bk << 3)]);
        }
        cp_commit();
    };

    float acc[4][8][4] = {};

    const int NC = KDIM / 64;
    issue(0);
    if (NC > 1) issue(1);

    for (int c = 0; c < NC; c++) {
        if (c == NC - 1) cp_wait<0>(); else cp_wait<1>();
        __syncthreads();
        if (c + 2 < NC) issue(c + 2);

        const uint32_t* As  = &sm[(c % 3) * STAGE_WORDS];
        const uint32_t* Ws_ = As + 4096;
        // four k16 steps per 64-K chunk; per row the k16 step ks occupies
        // 16B blocks 2ks (k 0..7 of the step) and 2ks+1 (k 8..15).
#pragma unroll
        for (int ks = 0; ks < 4; ks++) {
            uint32_t afr[4][4];
#pragma unroll
            for (int mt = 0; mt < 4; mt++) {
                int r  = (wm << 6) + (mt << 4) + g;
                int rs = r & 7;
                const uint32_t* a0 = &As[(r << 5)];
                const uint32_t* a1 = &As[((r + 8) << 5)];
                int w0 = (((2 * ks)     ^ rs) << 2) + tg;
                int w1 = (((2 * ks + 1) ^ rs) << 2) + tg;
                afr[mt][0] = a0[w0];
                afr[mt][1] = a1[w0];
                afr[mt][2] = a0[w1];
                afr[mt][3] = a1[w1];
            }
#pragma unroll
            for (int nt = 0; nt < 8; nt++) {
                int rb = (wn << 6) + (nt << 3) + g;
                int rs = rb & 7;
                const uint32_t* b = &Ws_[(rb << 5)];
                uint32_t bfr[2] = {b[(((2 * ks)     ^ rs) << 2) + tg],
                                   b[(((2 * ks + 1) ^ rs) << 2) + tg]};
#pragma unroll
                for (int mt = 0; mt < 4; mt++)
                    mma_f16(acc[mt][nt], afr[mt], bfr);
            }
        }
    }

    if (!FUSELN) {
#pragma unroll
        for (int mt = 0; mt < 4; mt++) {
            int row0 = m0 + (wm << 6) + (mt << 4) + g;
#pragma unroll
            for (int nt = 0; nt < 8; nt++) {
                int col = n0 + (wn << 6) + (nt << 3) + (tg << 1);
                float b0 = __ldg(&bias[col]);
                float b1 = __ldg(&bias[col + 1]);
                float v00 = acc[mt][nt][0] + b0, v01 = acc[mt][nt][1] + b1;
                float v10 = acc[mt][nt][2] + b0, v11 = acc[mt][nt][3] + b1;
                if (DOGELU) {
                    v00 = gelu_tanh(v00); v01 = gelu_tanh(v01);
                    v10 = gelu_tanh(v10); v11 = gelu_tanh(v11);
                }
                if (OUT16) {
                    __half* C = (__half*)Cout;
                    *(__half2*)&C[(size_t)row0 * N + col]       = __floats2half2_rn(v00, v01);
                    *(__half2*)&C[(size_t)(row0 + 8) * N + col] = __floats2half2_rn(v10, v11);
                } else {
                    float* C = (float*)Cout;
                    *(float2*)&C[(size_t)row0 * N + col]       = make_float2(v00, v01);
                    *(float2*)&C[(size_t)(row0 + 8) * N + col] = make_float2(v10, v11);
                }
            }
        }
    } else {
        // fused residual + LayerNorm over the full 128-col row (n0 == 0).
        float* C = (float*)Cout;
        __syncthreads();                      // all warps done with smem stages
        float* red = (float*)sm;              // [128 rows][2 wn][{sum,ss}]

        float psum[4][2], pss[4][2];
#pragma unroll
        for (int mt = 0; mt < 4; mt++)
#pragma unroll
            for (int rh = 0; rh < 2; rh++) {
                int row = m0 + (wm << 6) + (mt << 4) + (rh << 3) + g;
                const float* xr = Xres + (size_t)row * 128;
                float s = 0.f, ss = 0.f;
#pragma unroll
                for (int nt = 0; nt < 8; nt++) {
                    int col = (wn << 6) + (nt << 3) + (tg << 1);
                    float2 xv = *(const float2*)&xr[col];
                    float b0 = __ldg(&bias[col]);
                    float b1 = __ldg(&bias[col + 1]);
                    float v0 = acc[mt][nt][rh * 2 + 0] + b0 + xv.x;
                    float v1 = acc[mt][nt][rh * 2 + 1] + b1 + xv.y;
                    acc[mt][nt][rh * 2 + 0] = v0;
                    acc[mt][nt][rh * 2 + 1] = v1;
                    s  += v0 + v1;
                    ss += v0 * v0 + v1 * v1;
                }
                s  += __shfl_xor_sync(0xffffffffu, s, 1);
                s  += __shfl_xor_sync(0xffffffffu, s, 2);
                ss += __shfl_xor_sync(0xffffffffu, ss, 1);
                ss += __shfl_xor_sync(0xffffffffu, ss, 2);
                psum[mt][rh] = s;
                pss[mt][rh]  = ss;
            }
#pragma unroll
        for (int mt = 0; mt < 4; mt++)
#pragma unroll
            for (int rh = 0; rh < 2; rh++) {
                int rl = (wm << 6) + (mt << 4) + (rh << 3) + g;
                if (tg == 0) {
                    red[rl * 4 + wn * 2 + 0] = psum[mt][rh];
                    red[rl * 4 + wn * 2 + 1] = pss[mt][rh];
                }
            }
        __syncthreads();
#pragma unroll
        for (int mt = 0; mt < 4; mt++)
#pragma unroll
            for (int rh = 0; rh < 2; rh++) {
                int rl  = (wm << 6) + (mt << 4) + (rh << 3) + g;
                float s  = red[rl * 4 + 0] + red[rl * 4 + 2];
                float ss = red[rl * 4 + 1] + red[rl * 4 + 3];
                float mean = s * (1.0f / 128.0f);
                float var  = ss * (1.0f / 128.0f) - mean * mean;
                float rstd = rsqrtf(var + 1e-5f);
                int row = m0 + rl;
                float*  op  = C + (size_t)row * 128;
                __half* op16 = C16 ? C16 + (size_t)row * 128 : nullptr;
#pragma unroll
                for (int nt = 0; nt < 8; nt++) {
                    int col = (wn << 6) + (nt << 3) + (tg << 1);
                    float g0 = __ldg(&gamma[col]),     b0 = __ldg(&beta[col]);
                    float g1 = __ldg(&gamma[col + 1]), b1 = __ldg(&beta[col + 1]);
                    float o0 = (acc[mt][nt][rh * 2 + 0] - mean) * rstd * g0 + b0;
                    float o1 = (acc[mt][nt][rh * 2 + 1] - mean) * rstd * g1 + b1;
                    *(float2*)&op[col] = make_float2(o0, o1);
                    if (C16) *(__half2*)&op16[col] = __floats2half2_rn(o0, o1);
                }
            }
    }
}

// ---------------- temporal attention (seqlen T=12), f16 out -------------------
__global__ __launch_bounds__(96) void temporal_attn(
    const float* __restrict__ QKV, __half* __restrict__ Out) {
    __shared__ float s[TT * 384];
    int n = blockIdx.x;
    int b = blockIdx.y;
    for (int idx = threadIdx.x; idx < TT * 384; idx += 96) {
        int t = idx / 384, c = idx % 384;
        s[idx] = QKV[((size_t)(b * TT + t) * NS + n) * 384 + c];
    }
    __syncthreads();

    int h = threadIdx.x / TT;
    int q = threadIdx.x % TT;

    float qr[16];
#pragma unroll
    for (int d = 0; d < 16; d++) qr[d] = s[q * 384 + h * 16 + d];

    float sc[TT];
    float mx = -1e30f;
#pragma unroll
    for (int t2 = 0; t2 < TT; t2++) {
        const float* kr = &s[t2 * 384 + 128 + h * 16];
        float dot = 0.f;
#pragma unroll
        for (int d = 0; d < 16; d++) dot += qr[d] * kr[d];
        sc[t2] = dot * 0.25f;
        mx = fmaxf(mx, sc[t2]);
    }
    float l = 0.f;
#pragma unroll
    for (int t2 = 0; t2 < TT; t2++) {
        sc[t2] = __expf(sc[t2] - mx);
        l += sc[t2];
    }
    float acc[16] = {};
#pragma unroll
    for (int t2 = 0; t2 < TT; t2++) {
        float p = sc[t2];
        const float* vr = &s[t2 * 384 + 256 + h * 16];
#pragma unroll
        for (int d = 0; d < 16; d++) acc[d] += p * vr[d];
    }
    float inv = 1.f / l;
    __half* op = &Out[((size_t)(b * TT + q) * NS + n) * 128 + h * 16];
#pragma unroll
    for (int d = 0; d < 16; d += 2)
        *(__half2*)&op[d] = __floats2half2_rn(acc[d] * inv, acc[d + 1] * inv);
}

// ---------------- spatial attention via tensor cores, f16 out ----------------
__global__ __launch_bounds__(128) void spatial_attn_mma(
    const float* __restrict__ QKV, const float* __restrict__ Bias,
    __half* __restrict__ Out) {
    __shared__ uint32_t Ks [328 * 20];
    __shared__ uint32_t Vst[16 * 332];
    const int h  = blockIdx.x;
    const int bt = blockIdx.y;
    const size_t base = (size_t)bt * NS;
    const int tid = threadIdx.x;

    for (int idx = tid; idx < 328 * 16; idx += 128) {
        int key = idx >> 4, d = idx & 15;
        float kv = 0.f, vv = 0.f;
        if (key < NS) {
            const float* p = QKV + (base + key) * 384 + h * 16 + d;
            kv = p[128];
            vv = p[256];
        }
        Ks [key * 20 + d]   = f2tf32(kv);
        Vst[d * 332 + key]  = f2tf32(vv);
    }
    __syncthreads();

    const int warp = tid >> 5, lane = tid & 31;
    const int g = lane >> 2, tg = lane & 3;

    for (int qt = 0; qt < 6; qt++) {
        const int q0 = qt * 64 + warp * 16;
        if (q0 >= NS) break;

        const float* Qp0 = QKV + (base + q0 + g) * 384 + h * 16;
        const float* Qp1 = Qp0 + 8 * 384;
        float2 q00 = *(const float2*)(Qp0 + 2 * tg);
        float2 q01 = *(const float2*)(Qp0 + 8 + 2 * tg);
        float2 q10 = *(const float2*)(Qp1 + 2 * tg);
        float2 q11 = *(const float2*)(Qp1 + 8 + 2 * tg);
        uint32_t qa0[4] = {f2tf32(q00.x), f2tf32(q10.x), f2tf32(q00.y), f2tf32(q10.y)};
        uint32_t qa1[4] = {f2tf32(q01.x), f2tf32(q11.x), f2tf32(q01.y), f2tf32(q11.y)};

        const int qr0 = min(q0 + g, NS - 1);
        const int qr1 = min(q0 + g + 8, NS - 1);
        const float* brow0 = Bias + (size_t)qr0 * NS;
        const float* brow1 = Bias + (size_t)qr1 * NS;

        float o0[4] = {0.f, 0.f, 0.f, 0.f};
        float o1[4] = {0.f, 0.f, 0.f, 0.f};
        float l0 = 0.f, l1 = 0.f;

        for (int nt = 0; nt < 40; nt++) {
            const int k0 = nt * 8;
            float c[4] = {0.f, 0.f, 0.f, 0.f};
            {
                uint2 b = *(const uint2*)&Ks[(k0 + g) * 20 + 2 * tg];
                uint32_t bf[2] = {b.x, b.y};
                mma_tf32(c, qa0, bf);
            }
            {
                uint2 b = *(const uint2*)&Ks[(k0 + g) * 20 + 8 + 2 * tg];
                uint32_t bf[2] = {b.x, b.y};
                mma_tf32(c, qa1, bf);
            }
            const int col0 = k0 + 2 * tg;
            float p0 = __expf(c[0] * 0.25f + __ldg(brow0 + col0));
            float p1 = __expf(c[1] * 0.25f + __ldg(brow0 + col0 + 1));
            float p2 = __expf(c[2] * 0.25f + __ldg(brow1 + col0));
            float p3 = __expf(c[3] * 0.25f + __ldg(brow1 + col0 + 1));
            l0 += p0 + p1;
            l1 += p2 + p3;
            uint32_t pa[4] = {f2tf32(p0), f2tf32(p2), f2tf32(p1), f2tf32(p3)};
            {
                uint2 vb = *(const uint2*)&Vst[g * 332 + col0];
                uint32_t bf[2] = {vb.x, vb.y};
                mma_tf32(o0, pa, bf);
            }
            {
                uint2 vb = *(const uint2*)&Vst[(8 + g) * 332 + col0];
                uint32_t bf[2] = {vb.x, vb.y};
                mma_tf32(o1, pa, bf);
            }
        }
        {
            const int k0 = 320;
            float c[4] = {0.f, 0.f, 0.f, 0.f};
            {
                uint2 b = *(const uint2*)&Ks[(k0 + g) * 20 + 2 * tg];
                uint32_t bf[2] = {b.x, b.y};
                mma_tf32(c, qa0, bf);
            }
            {
                uint2 b = *(const uint2*)&Ks[(k0 + g) * 20 + 8 + 2 * tg];
                uint32_t bf[2] = {b.x, b.y};
                mma_tf32(c, qa1, bf);
            }
            const int col0 = k0 + 2 * tg;
            const int col1 = col0 + 1;
            float p0 = (col0 < NS) ? __expf(c[0] * 0.25f + __ldg(brow0 + col0)) : 0.f;
            float p1 = (col1 < NS) ? __expf(c[1] * 0.25f + __ldg(brow0 + col1)) : 0.f;
            float p2 = (col0 < NS) ? __expf(c[2] * 0.25f + __ldg(brow1 + col0)) : 0.f;
            float p3 = (col1 < NS) ? __expf(c[3] * 0.25f + __ldg(brow1 + col1)) : 0.f;
            l0 += p0 + p1;
            l1 += p2 + p3;
            uint32_t pa[4] = {f2tf32(p0), f2tf32(p2), f2tf32(p1), f2tf32(p3)};
            {
                uint2 vb = *(const uint2*)&Vst[g * 332 + col0];
                uint32_t bf[2] = {vb.x, vb.y};
                mma_tf32(o0, pa, bf);
            }
            {
                uint2 vb = *(const uint2*)&Vst[(8 + g) * 332 + col0];
                uint32_t bf[2] = {vb.x, vb.y};
                mma_tf32(o1, pa, bf);
            }
        }

        l0 += __shfl_xor_sync(0xffffffffu, l0, 1);
        l0 += __shfl_xor_sync(0xffffffffu, l0, 2);
        l1 += __shfl_xor_sync(0xffffffffu, l1, 1);
        l1 += __shfl_xor_sync(0xffffffffu, l1, 2);
        float inv0 = 1.f / l0;
        float inv1 = 1.f / l1;

        if (q0 + g < NS) {
            __half* op = Out + (base + q0 + g) * 128 + h * 16;
            *(__half2*)(op + 2 * tg)     = __floats2half2_rn(o0[0] * inv0, o0[1] * inv0);
            *(__half2*)(op + 8 + 2 * tg) = __floats2half2_rn(o1[0] * inv0, o1[1] * inv0);
        }
        if (q0 + g + 8 < NS) {
            __half* op = Out + (base + q0 + g + 8) * 128 + h * 16;
            *(__half2*)(op + 2 * tg)     = __floats2half2_rn(o0[2] * inv1, o0[3] * inv1);
            *(__half2*)(op + 8 + 2 * tg) = __floats2half2_rn(o1[2] * inv1, o1[3] * inv1);
        }
    }
}

// ---------------- driver ------------------------------------------------------
extern "C" void kernel_launch(void* const* d_in, const int* in_sizes, int n_in,
                              void* d_out, int out_size) {
    const float* x        = (const float*)d_in[0];
    const float* t_w_in   = (const float*)d_in[1];
    const float* t_b_in   = (const float*)d_in[2];
    const float* t_w_out  = (const float*)d_in[3];
    const float* t_b_out  = (const float*)d_in[4];
    const float* s_w_in   = (const float*)d_in[5];
    const float* s_b_in   = (const float*)d_in[6];
    const float* s_w_out  = (const float*)d_in[7];
    const float* s_b_out  = (const float*)d_in[8];
    const float* g_bias   = (const float*)d_in[9];
    const float* norm_t_g = (const float*)d_in[10];
    const float* norm_t_b = (const float*)d_in[11];
    const float* norm_s_g = (const float*)d_in[12];
    const float* norm_s_b = (const float*)d_in[13];
    const float* ff_w1    = (const float*)d_in[14];
    const float* ff_b1    = (const float*)d_in[15];
    const float* ff_w2    = (const float*)d_in[16];
    const float* ff_b2    = (const float*)d_in[17];
    const float* norm_f_g = (const float*)d_in[18];
    const float* norm_f_b = (const float*)d_in[19];
    float* out = (float*)d_out;

    float  *buf, *x1, *x2;
    __half *h16, *attn16, *x116, *x216, *x16, *w16;
    cudaGetSymbolAddress((void**)&buf,    g_buf);
    cudaGetSymbolAddress((void**)&h16,    g_h16);
    cudaGetSymbolAddress((void**)&attn16, g_attn16);
    cudaGetSymbolAddress((void**)&x1,     g_x1);
    cudaGetSymbolAddress((void**)&x116,   g_x116);
    cudaGetSymbolAddress((void**)&x2,     g_x2);
    cudaGetSymbolAddress((void**)&x216,   g_x216);
    cudaGetSymbolAddress((void**)&x16,    g_x16);
    cudaGetSymbolAddress((void**)&w16,    g_w16);

    cudaFuncSetAttribute(gemm_f16<128, false, false, false>, cudaFuncAttributeMaxDynamicSharedMemorySize, GEMM_SMEM_BYTES);
    cudaFuncSetAttribute(gemm_f16<128, false, true,  false>, cudaFuncAttributeMaxDynamicSharedMemorySize, GEMM_SMEM_BYTES);
    cudaFuncSetAttribute(gemm_f16<128, true,  false, true >, cudaFuncAttributeMaxDynamicSharedMemorySize, GEMM_SMEM_BYTES);
    cudaFuncSetAttribute(gemm_f16<512, false, true,  false>, cudaFuncAttributeMaxDynamicSharedMemorySize, GEMM_SMEM_BYTES);

    const int MB = MTOK / 128;   // 975

    // --- f16 conversions: input + all weights ---
    conv_f16<<<(MTOK * 128 / 4 + 255) / 256, 256>>>(x, x16, MTOK * 128 / 4);
    conv_f16<<<48, 256>>>(t_w_in,  w16 + W_T_IN,  49152 / 4);
    conv_f16<<<16, 256>>>(t_w_out, w16 + W_T_OUT, 16384 / 4);
    conv_f16<<<48, 256>>>(s_w_in,  w16 + W_S_IN,  49152 / 4);
    conv_f16<<<16, 256>>>(s_w_out, w16 + W_S_OUT, 16384 / 4);
    conv_f16<<<64, 256>>>(ff_w1,   w16 + W_FF1,   65536 / 4);
    conv_f16<<<64, 256>>>(ff_w2,   w16 + W_FF2,   65536 / 4);

    // --- temporal block ---
    gemm_f16<128, false, false, false><<<dim3(3, MB), 128, GEMM_SMEM_BYTES>>>(
        x16, w16 + W_T_IN, t_b_in, buf, 384, nullptr, nullptr, nullptr, nullptr);
    temporal_attn<<<dim3(NS, BB), 96>>>(buf, attn16);
    gemm_f16<128, false, true, false><<<dim3(1, MB), 128, GEMM_SMEM_BYTES>>>(
        attn16, w16 + W_T_OUT, t_b_out, x1, 128, x, norm_t_g, norm_t_b, x116);

    // --- spatial block ---
    gemm_f16<128, false, false, false><<<dim3(3, MB), 128, GEMM_SMEM_BYTES>>>(
        x116, w16 + W_S_IN, s_b_in, buf, 384, nullptr, nullptr, nullptr, nullptr);
    spatial_attn_mma<<<dim3(8, BB * TT), 128>>>(buf, g_bias, attn16);
    gemm_f16<128, false, true, false><<<dim3(1, MB), 128, GEMM_SMEM_BYTES>>>(
        attn16, w16 + W_S_OUT, s_b_out, x2, 128, x1, norm_s_g, norm_s_b, x216);

    // --- FFN ---
    gemm_f16<128, true, false, true><<<dim3(4, MB), 128, GEMM_SMEM_BYTES>>>(
        x216, w16 + W_FF1, ff_b1, h16, 512, nullptr, nullptr, nullptr, nullptr);
    gemm_f16<512, false, true, false><<<dim3(1, MB), 128, GEMM_SMEM_BYTES>>>(
        h16, w16 + W_FF2, ff_b2, out, 128, x2, norm_f_g, norm_f_b, nullptr);
}

// round 17
// speedup vs baseline: 1.5732x; 1.1058x over previous
#include <cuda_runtime.h>
#include <cuda_fp16.h>
#include <math.h>
#include <stdint.h>

// Problem constants
#define BB 32
#define TT 12
#define NS 325
#define DD 128
#define FF 512
#define MTOK (BB*TT*NS)   // 124800 tokens = 975 * 128 exactly

// ---------------- scratch (static device allocations; no runtime alloc) ------
__device__ __half g_buf16[(size_t)MTOK * 384];   // QKV, f16
__device__ __half g_h16  [(size_t)MTOK * 512];   // FFN hidden, f16
__device__ __half g_attn16[(size_t)MTOK * 128];  // attention out, f16
__device__ float  g_x1   [(size_t)MTOK * 128];
__device__ __half g_x116 [(size_t)MTOK * 128];
__device__ float  g_x2   [(size_t)MTOK * 128];
__device__ __half g_x216 [(size_t)MTOK * 128];
__device__ __half g_x16  [(size_t)MTOK * 128];   // f16 copy of input x
__device__ __half g_w16  [262144];               // all 6 weight matrices, f16

// weight pool offsets (elements)
#define W_T_IN   0
#define W_T_OUT  49152
#define W_S_IN   65536
#define W_S_OUT  114688
#define W_FF1    131072
#define W_FF2    196608

// ---------------- helpers ----------------------------------------------------
__device__ __forceinline__ float gelu_tanh(float x) {
    float x3 = x * x * x;
    float t  = tanhf(0.7978845608028654f * (x + 0.044715f * x3));
    return 0.5f * x * (1.0f + t);
}

__device__ __forceinline__ uint32_t pack_h2(float a, float b) {
    __half2 h = __floats2half2_rn(a, b);
    return *(uint32_t*)&h;
}

__device__ __forceinline__ void mma_f16(float c[4], const uint32_t a[4], const uint32_t b[2]) {
    asm volatile(
        "mma.sync.aligned.m16n8k16.row.col.f32.f16.f16.f32 "
        "{%0,%1,%2,%3}, {%4,%5,%6,%7}, {%8,%9}, {%0,%1,%2,%3};"
        : "+f"(c[0]), "+f"(c[1]), "+f"(c[2]), "+f"(c[3])
        : "r"(a[0]), "r"(a[1]), "r"(a[2]), "r"(a[3]), "r"(b[0]), "r"(b[1]));
}

__device__ __forceinline__ void cp_async16(uint32_t smem_addr, const void* gptr) {
    asm volatile("cp.async.cg.shared.global [%0], [%1], 16;\n"
                 :: "r"(smem_addr), "l"(gptr));
}
__device__ __forceinline__ void cp_commit() {
    asm volatile("cp.async.commit_group;\n" ::: "memory");
}
template<int N>
__device__ __forceinline__ void cp_wait() {
    asm volatile("cp.async.wait_group %0;\n" :: "n"(N) : "memory");
}

// ---------------- conversions -------------------------------------------------
__global__ void conv_f16(const float* __restrict__ in, __half* __restrict__ out, int n4) {
    int i = blockIdx.x * blockDim.x + threadIdx.x;
    if (i < n4) {
        float4 v = ((const float4*)in)[i];
        ((__half2*)out)[2 * i]     = __floats2half2_rn(v.x, v.y);
        ((__half2*)out)[2 * i + 1] = __floats2half2_rn(v.z, v.w);
    }
}

// all 6 weight matrices in one launch; segments by float4 index.
__global__ void conv_weights(
    const float* __restrict__ w0, const float* __restrict__ w1,
    const float* __restrict__ w2, const float* __restrict__ w3,
    const float* __restrict__ w4, const float* __restrict__ w5,
    __half* __restrict__ out) {
    int i = blockIdx.x * blockDim.x + threadIdx.x;   // 0..65535 (float4 units)
    const float* src; int o;
    if      (i < 12288) { src = w0; o = i;          }
    else if (i < 16384) { src = w1; o = i - 12288;  }
    else if (i < 28672) { src = w2; o = i - 16384;  }
    else if (i < 32768) { src = w3; o = i - 28672;  }
    else if (i < 49152) { src = w4; o = i - 32768;  }
    else                { src = w5; o = i - 49152;  }
    float4 v = ((const float4*)src)[o];
    ((__half2*)out)[2 * i]     = __floats2half2_rn(v.x, v.y);
    ((__half2*)out)[2 * i + 1] = __floats2half2_rn(v.z, v.w);
}

// ---------------- FP16-operand tensor-core GEMM, cp.async 3-stage ------------
// C[M,N] = A16[M,K] @ W16[N,K]^T + bias; optional gelu / fused residual+LN.
// K chunk 64 (128B f16 rows), stage 32KB, 3 stages = 96KB -> 2 CTAs/SM.
// 128 thr, 4 warps (2Mx2N), warp tile 64x64, zero cvt in the inner loop
// (LDS.32 f16x2 fragments, conflict-free 16B-block XOR swizzle).
// OUT16: f16 output (QKV, FFN1). FUSELN: fp32 out + optional f16 copy.
#define STAGE_WORDS 8192   // (128 + 128) rows * 32 words
#define GEMM_SMEM_BYTES (3 * STAGE_WORDS * 4)   // 98304

template<int KDIM, bool DOGELU, bool FUSELN, bool OUT16>
__global__ __launch_bounds__(128, 2) void gemm_f16(
    const __half* __restrict__ A, const __half* __restrict__ W,
    const float* __restrict__ bias, void* __restrict__ Cout, int N,
    const float* __restrict__ Xres, const float* __restrict__ gamma,
    const float* __restrict__ beta, __half* __restrict__ C16) {
    extern __shared__ uint32_t sm[];

    const int tid  = threadIdx.x;
    const int warp = tid >> 5, lane = tid & 31;
    const int wm = warp & 1, wn = warp >> 1;
    const int g  = lane >> 2, tg = lane & 3;
    const int m0 = blockIdx.y << 7;
    const int n0 = blockIdx.x << 7;

    const int rr = tid >> 3;   // copy row base (0..15)
    const int bk = tid & 7;    // 16B block within 128B row

    auto issue = [&](int c) {
        const int st = c % 3;
        const int k0 = c << 6;
        uint32_t baseA = (uint32_t)__cvta_generic_to_shared(&sm[st * STAGE_WORDS]);
        uint32_t baseW = baseA + 4096 * 4;
#pragma unroll
        for (int i = 0; i < 8; i++) {
            int r = rr + (i << 4);
            uint32_t off = ((r << 5) + ((bk ^ (r & 7)) << 2)) << 2;
            cp_async16(baseA + off, &A[(size_t)(m0 + r) * KDIM + k0 + (bk << 3)]);
            cp_async16(baseW + off, &W[(size_t)(n0 + r) * KDIM + k0 + (bk << 3)]);
        }
        cp_commit();
    };

    float acc[4][8][4] = {};

    const int NC = KDIM / 64;
    issue(0);
    if (NC > 1) issue(1);

    for (int c = 0; c < NC; c++) {
        if (c == NC - 1) cp_wait<0>(); else cp_wait<1>();
        __syncthreads();
        if (c + 2 < NC) issue(c + 2);

        const uint32_t* As  = &sm[(c % 3) * STAGE_WORDS];
        const uint32_t* Ws_ = As + 4096;
#pragma unroll
        for (int ks = 0; ks < 4; ks++) {
            uint32_t afr[4][4];
#pragma unroll
            for (int mt = 0; mt < 4; mt++) {
                int r  = (wm << 6) + (mt << 4) + g;
                int rs = r & 7;
                const uint32_t* a0 = &As[(r << 5)];
                const uint32_t* a1 = &As[((r + 8) << 5)];
                int w0 = (((2 * ks)     ^ rs) << 2) + tg;
                int w1 = (((2 * ks + 1) ^ rs) << 2) + tg;
                afr[mt][0] = a0[w0];
                afr[mt][1] = a1[w0];
                afr[mt][2] = a0[w1];
                afr[mt][3] = a1[w1];
            }
#pragma unroll
            for (int nt = 0; nt < 8; nt++) {
                int rb = (wn << 6) + (nt << 3) + g;
                int rs = rb & 7;
                const uint32_t* b = &Ws_[(rb << 5)];
                uint32_t bfr[2] = {b[(((2 * ks)     ^ rs) << 2) + tg],
                                   b[(((2 * ks + 1) ^ rs) << 2) + tg]};
#pragma unroll
                for (int mt = 0; mt < 4; mt++)
                    mma_f16(acc[mt][nt], afr[mt], bfr);
            }
        }
    }

    if (!FUSELN) {
#pragma unroll
        for (int mt = 0; mt < 4; mt++) {
            int row0 = m0 + (wm << 6) + (mt << 4) + g;
#pragma unroll
            for (int nt = 0; nt < 8; nt++) {
                int col = n0 + (wn << 6) + (nt << 3) + (tg << 1);
                float b0 = __ldg(&bias[col]);
                float b1 = __ldg(&bias[col + 1]);
                float v00 = acc[mt][nt][0] + b0, v01 = acc[mt][nt][1] + b1;
                float v10 = acc[mt][nt][2] + b0, v11 = acc[mt][nt][3] + b1;
                if (DOGELU) {
                    v00 = gelu_tanh(v00); v01 = gelu_tanh(v01);
                    v10 = gelu_tanh(v10); v11 = gelu_tanh(v11);
                }
                if (OUT16) {
                    __half* C = (__half*)Cout;
                    *(__half2*)&C[(size_t)row0 * N + col]       = __floats2half2_rn(v00, v01);
                    *(__half2*)&C[(size_t)(row0 + 8) * N + col] = __floats2half2_rn(v10, v11);
                } else {
                    float* C = (float*)Cout;
                    *(float2*)&C[(size_t)row0 * N + col]       = make_float2(v00, v01);
                    *(float2*)&C[(size_t)(row0 + 8) * N + col] = make_float2(v10, v11);
                }
            }
        }
    } else {
        float* C = (float*)Cout;
        __syncthreads();
        float* red = (float*)sm;

        float psum[4][2], pss[4][2];
#pragma unroll
        for (int mt = 0; mt < 4; mt++)
#pragma unroll
            for (int rh = 0; rh < 2; rh++) {
                int row = m0 + (wm << 6) + (mt << 4) + (rh << 3) + g;
                const float* xr = Xres + (size_t)row * 128;
                float s = 0.f, ss = 0.f;
#pragma unroll
                for (int nt = 0; nt < 8; nt++) {
                    int col = (wn << 6) + (nt << 3) + (tg << 1);
                    float2 xv = *(const float2*)&xr[col];
                    float b0 = __ldg(&bias[col]);
                    float b1 = __ldg(&bias[col + 1]);
                    float v0 = acc[mt][nt][rh * 2 + 0] + b0 + xv.x;
                    float v1 = acc[mt][nt][rh * 2 + 1] + b1 + xv.y;
                    acc[mt][nt][rh * 2 + 0] = v0;
                    acc[mt][nt][rh * 2 + 1] = v1;
                    s  += v0 + v1;
                    ss += v0 * v0 + v1 * v1;
                }
                s  += __shfl_xor_sync(0xffffffffu, s, 1);
                s  += __shfl_xor_sync(0xffffffffu, s, 2);
                ss += __shfl_xor_sync(0xffffffffu, ss, 1);
                ss += __shfl_xor_sync(0xffffffffu, ss, 2);
                psum[mt][rh] = s;
                pss[mt][rh]  = ss;
            }
#pragma unroll
        for (int mt = 0; mt < 4; mt++)
#pragma unroll
            for (int rh = 0; rh < 2; rh++) {
                int rl = (wm << 6) + (mt << 4) + (rh << 3) + g;
                if (tg == 0) {
                    red[rl * 4 + wn * 2 + 0] = psum[mt][rh];
                    red[rl * 4 + wn * 2 + 1] = pss[mt][rh];
                }
            }
        __syncthreads();
#pragma unroll
        for (int mt = 0; mt < 4; mt++)
#pragma unroll
            for (int rh = 0; rh < 2; rh++) {
                int rl  = (wm << 6) + (mt << 4) + (rh << 3) + g;
                float s  = red[rl * 4 + 0] + red[rl * 4 + 2];
                float ss = red[rl * 4 + 1] + red[rl * 4 + 3];
                float mean = s * (1.0f / 128.0f);
                float var  = ss * (1.0f / 128.0f) - mean * mean;
                float rstd = rsqrtf(var + 1e-5f);
                int row = m0 + rl;
                float*  op   = C + (size_t)row * 128;
                __half* op16 = C16 ? C16 + (size_t)row * 128 : nullptr;
#pragma unroll
                for (int nt = 0; nt < 8; nt++) {
                    int col = (wn << 6) + (nt << 3) + (tg << 1);
                    float g0 = __ldg(&gamma[col]),     b0 = __ldg(&beta[col]);
                    float g1 = __ldg(&gamma[col + 1]), b1 = __ldg(&beta[col + 1]);
                    float o0 = (acc[mt][nt][rh * 2 + 0] - mean) * rstd * g0 + b0;
                    float o1 = (acc[mt][nt][rh * 2 + 1] - mean) * rstd * g1 + b1;
                    *(float2*)&op[col] = make_float2(o0, o1);
                    if (C16) *(__half2*)&op16[col] = __floats2half2_rn(o0, o1);
                }
            }
    }
}

// ---------------- temporal attention (seqlen T=12), f16 in/out ----------------
__global__ __launch_bounds__(96) void temporal_attn(
    const __half* __restrict__ QKV, __half* __restrict__ Out) {
    __shared__ __half s[TT * 384];
    int n = blockIdx.x;
    int b = blockIdx.y;
    for (int idx = threadIdx.x; idx < TT * 192; idx += 96) {
        int t = idx / 192, c2 = idx % 192;
        *(__half2*)&s[t * 384 + 2 * c2] =
            *(const __half2*)&QKV[((size_t)(b * TT + t) * NS + n) * 384 + 2 * c2];
    }
    __syncthreads();

    int h = threadIdx.x / TT;
    int q = threadIdx.x % TT;

    float qr[16];
#pragma unroll
    for (int d = 0; d < 16; d++) qr[d] = __half2float(s[q * 384 + h * 16 + d]);

    float sc[TT];
    float mx = -1e30f;
#pragma unroll
    for (int t2 = 0; t2 < TT; t2++) {
        const __half* kr = &s[t2 * 384 + 128 + h * 16];
        float dot = 0.f;
#pragma unroll
        for (int d = 0; d < 16; d++) dot += qr[d] * __half2float(kr[d]);
        sc[t2] = dot * 0.25f;
        mx = fmaxf(mx, sc[t2]);
    }
    float l = 0.f;
#pragma unroll
    for (int t2 = 0; t2 < TT; t2++) {
        sc[t2] = __expf(sc[t2] - mx);
        l += sc[t2];
    }
    float acc[16] = {};
#pragma unroll
    for (int t2 = 0; t2 < TT; t2++) {
        float p = sc[t2];
        const __half* vr = &s[t2 * 384 + 256 + h * 16];
#pragma unroll
        for (int d = 0; d < 16; d++) acc[d] += p * __half2float(vr[d]);
    }
    float inv = 1.f / l;
    __half* op = &Out[((size_t)(b * TT + q) * NS + n) * 128 + h * 16];
#pragma unroll
    for (int d = 0; d < 16; d += 2)
        *(__half2*)&op[d] = __floats2half2_rn(acc[d] * inv, acc[d + 1] * inv);
}

// ---------------- spatial attention, full f16 k16 mma -------------------------
// Block (h, bt), 128 threads = 4 warps. Keys padded to 336 (21 pairs of 16).
// Ks [336 keys][18 halfs] (d-major rows); Vt [16 d][340 halfs] (key-major).
// Per warp/16-query tile, per 16-key pair: 2 QK mma (m16n8k16, full d=16 in
// one instruction) + 2 PV mma (k16 keys) = 4 mmas per 16 keys — half of the
// old tf32-k8 count. S accumulators pack directly into the PV A-fragment.
#define KSTR 18
#define VSTR 340
__global__ __launch_bounds__(128) void spatial_attn_f16(
    const __half* __restrict__ QKV, const float* __restrict__ Bias,
    __half* __restrict__ Out) {
    __shared__ __half Ks[336 * KSTR];
    __shared__ __half Vt[16 * VSTR];
    const int h  = blockIdx.x;
    const int bt = blockIdx.y;
    const size_t base = (size_t)bt * NS;
    const int tid = threadIdx.x;

    // fill: 336 keys x 8 half2 (d pairs)
    for (int idx = tid; idx < 336 * 8; idx += 128) {
        int key = idx >> 3, d2 = idx & 7;
        __half2 kv = __float2half2_rn(0.f), vv = __float2half2_rn(0.f);
        if (key < NS) {
            const __half* p = QKV + (base + key) * 384 + h * 16 + 2 * d2;
            kv = *(const __half2*)(p + 128);
            vv = *(const __half2*)(p + 256);
        }
        *(__half2*)&Ks[key * KSTR + 2 * d2] = kv;
        Vt[(2 * d2)     * VSTR + key] = __low2half(vv);
        Vt[(2 * d2 + 1) * VSTR + key] = __high2half(vv);
    }
    __syncthreads();

    const int warp = tid >> 5, lane = tid & 31;
    const int g = lane >> 2, tg = lane & 3;
    const float scale_h = 0.25f;   // 1/sqrt(16)

    for (int qt = 0; qt < 6; qt++) {
        const int q0 = qt * 64 + warp * 16;
        if (q0 >= NS) break;

        // Q fragment (f16, held across key pairs)
        const __half* Qp0 = QKV + (base + q0 + g) * 384 + h * 16;
        const __half* Qp1 = Qp0 + 8 * 384;
        uint32_t qa[4];
        qa[0] = *(const uint32_t*)(Qp0 + 2 * tg);
        qa[1] = *(const uint32_t*)(Qp1 + 2 * tg);
        qa[2] = *(const uint32_t*)(Qp0 + 8 + 2 * tg);
        qa[3] = *(const uint32_t*)(Qp1 + 8 + 2 * tg);

        const int qr0 = min(q0 + g, NS - 1);
        const int qr1 = min(q0 + g + 8, NS - 1);
        const float* brow0 = Bias + (size_t)qr0 * NS;
        const float* brow1 = Bias + (size_t)qr1 * NS;

        float od0[4] = {0.f, 0.f, 0.f, 0.f};   // d 0..7
        float od1[4] = {0.f, 0.f, 0.f, 0.f};   // d 8..15
        float l0 = 0.f, l1 = 0.f;

#pragma unroll 2
        for (int pr = 0; pr < 21; pr++) {
            const int k0 = pr * 16;
            // S for keys k0..k0+7 and k0+8..k0+15
            float c1[4] = {0.f, 0.f, 0.f, 0.f};
            float c2[4] = {0.f, 0.f, 0.f, 0.f};
            {
                const __half* kp = &Ks[(k0 + g) * KSTR + 2 * tg];
                uint32_t bf[2] = {*(const uint32_t*)kp, *(const uint32_t*)(kp + 8)};
                mma_f16(c1, qa, bf);
            }
            {
                const __half* kp = &Ks[(k0 + 8 + g) * KSTR + 2 * tg];
                uint32_t bf[2] = {*(const uint32_t*)kp, *(const uint32_t*)(kp + 8)};
                mma_f16(c2, qa, bf);
            }
            const int colA = k0 + 2 * tg;        // keys for c1
            const int colB = k0 + 8 + 2 * tg;    // keys for c2
            float p10, p11, p12, p13, p20, p21, p22, p23;
            if (pr < 20) {                        // all keys valid
                p10 = __expf(c1[0] * scale_h + __ldg(brow0 + colA));
                p11 = __expf(c1[1] * scale_h + __ldg(brow0 + colA + 1));
                p12 = __expf(c1[2] * scale_h + __ldg(brow1 + colA));
                p13 = __expf(c1[3] * scale_h + __ldg(brow1 + colA + 1));
                p20 = __expf(c2[0] * scale_h + __ldg(brow0 + colB));
                p21 = __expf(c2[1] * scale_h + __ldg(brow0 + colB + 1));
                p22 = __expf(c2[2] * scale_h + __ldg(brow1 + colB));
                p23 = __expf(c2[3] * scale_h + __ldg(brow1 + colB + 1));
            } else {                              // tail: keys 320..335
                p10 = (colA     < NS) ? __expf(c1[0] * scale_h + __ldg(brow0 + colA))     : 0.f;
                p11 = (colA + 1 < NS) ? __expf(c1[1] * scale_h + __ldg(brow0 + colA + 1)) : 0.f;
                p12 = (colA     < NS) ? __expf(c1[2] * scale_h + __ldg(brow1 + colA))     : 0.f;
                p13 = (colA + 1 < NS) ? __expf(c1[3] * scale_h + __ldg(brow1 + colA + 1)) : 0.f;
                p20 = (colB     < NS) ? __expf(c2[0] * scale_h + __ldg(brow0 + colB))     : 0.f;
                p21 = (colB + 1 < NS) ? __expf(c2[1] * scale_h + __ldg(brow0 + colB + 1)) : 0.f;
                p22 = (colB     < NS) ? __expf(c2[2] * scale_h + __ldg(brow1 + colB))     : 0.f;
                p23 = (colB + 1 < NS) ? __expf(c2[3] * scale_h + __ldg(brow1 + colB + 1)) : 0.f;
            }
            l0 += p10 + p11 + p20 + p21;
            l1 += p12 + p13 + p22 + p23;

            // PV: A fragment from P (rows g/g+8, k = keys)
            uint32_t pa[4];
            pa[0] = pack_h2(p10, p11);
            pa[1] = pack_h2(p12, p13);
            pa[2] = pack_h2(p20, p21);
            pa[3] = pack_h2(p22, p23);
            {
                const __half* vp = &Vt[g * VSTR + k0 + 2 * tg];
                uint32_t bf[2] = {*(const uint32_t*)vp, *(const uint32_t*)(vp + 8)};
                mma_f16(od0, pa, bf);
            }
            {
                const __half* vp = &Vt[(8 + g) * VSTR + k0 + 2 * tg];
                uint32_t bf[2] = {*(const uint32_t*)vp, *(const uint32_t*)(vp + 8)};
                mma_f16(od1, pa, bf);
            }
        }

        l0 += __shfl_xor_sync(0xffffffffu, l0, 1);
        l0 += __shfl_xor_sync(0xffffffffu, l0, 2);
        l1 += __shfl_xor_sync(0xffffffffu, l1, 1);
        l1 += __shfl_xor_sync(0xffffffffu, l1, 2);
        float inv0 = 1.f / l0;
        float inv1 = 1.f / l1;

        if (q0 + g < NS) {
            __half* op = Out + (base + q0 + g) * 128 + h * 16;
            *(__half2*)(op + 2 * tg)     = __floats2half2_rn(od0[0] * inv0, od0[1] * inv0);
            *(__half2*)(op + 8 + 2 * tg) = __floats2half2_rn(od1[0] * inv0, od1[1] * inv0);
        }
        if (q0 + g + 8 < NS) {
            __half* op = Out + (base + q0 + g + 8) * 128 + h * 16;
            *(__half2*)(op + 2 * tg)     = __floats2half2_rn(od0[2] * inv1, od0[3] * inv1);
            *(__half2*)(op + 8 + 2 * tg) = __floats2half2_rn(od1[2] * inv1, od1[3] * inv1);
        }
    }
}

// ---------------- driver ------------------------------------------------------
extern "C" void kernel_launch(void* const* d_in, const int* in_sizes, int n_in,
                              void* d_out, int out_size) {
    const float* x        = (const float*)d_in[0];
    const float* t_w_in   = (const float*)d_in[1];
    const float* t_b_in   = (const float*)d_in[2];
    const float* t_w_out  = (const float*)d_in[3];
    const float* t_b_out  = (const float*)d_in[4];
    const float* s_w_in   = (const float*)d_in[5];
    const float* s_b_in   = (const float*)d_in[6];
    const float* s_w_out  = (const float*)d_in[7];
    const float* s_b_out  = (const float*)d_in[8];
    const float* g_bias   = (const float*)d_in[9];
    const float* norm_t_g = (const float*)d_in[10];
    const float* norm_t_b = (const float*)d_in[11];
    const float* norm_s_g = (const float*)d_in[12];
    const float* norm_s_b = (const float*)d_in[13];
    const float* ff_w1    = (const float*)d_in[14];
    const float* ff_b1    = (const float*)d_in[15];
    const float* ff_w2    = (const float*)d_in[16];
    const float* ff_b2    = (const float*)d_in[17];
    const float* norm_f_g = (const float*)d_in[18];
    const float* norm_f_b = (const float*)d_in[19];
    float* out = (float*)d_out;

    float  *x1, *x2;
    __half *buf16, *h16, *attn16, *x116, *x216, *x16, *w16;
    cudaGetSymbolAddress((void**)&buf16,  g_buf16);
    cudaGetSymbolAddress((void**)&h16,    g_h16);
    cudaGetSymbolAddress((void**)&attn16, g_attn16);
    cudaGetSymbolAddress((void**)&x1,     g_x1);
    cudaGetSymbolAddress((void**)&x116,   g_x116);
    cudaGetSymbolAddress((void**)&x2,     g_x2);
    cudaGetSymbolAddress((void**)&x216,   g_x216);
    cudaGetSymbolAddress((void**)&x16,    g_x16);
    cudaGetSymbolAddress((void**)&w16,    g_w16);

    cudaFuncSetAttribute(gemm_f16<128, false, false, true >, cudaFuncAttributeMaxDynamicSharedMemorySize, GEMM_SMEM_BYTES);
    cudaFuncSetAttribute(gemm_f16<128, false, true,  false>, cudaFuncAttributeMaxDynamicSharedMemorySize, GEMM_SMEM_BYTES);
    cudaFuncSetAttribute(gemm_f16<128, true,  false, true >, cudaFuncAttributeMaxDynamicSharedMemorySize, GEMM_SMEM_BYTES);
    cudaFuncSetAttribute(gemm_f16<512, false, true,  false>, cudaFuncAttributeMaxDynamicSharedMemorySize, GEMM_SMEM_BYTES);

    const int MB = MTOK / 128;   // 975

    // --- f16 conversions: input + all weights (one launch each) ---
    conv_f16<<<(MTOK * 128 / 4 + 255) / 256, 256>>>(x, x16, MTOK * 128 / 4);
    conv_weights<<<256, 256>>>(t_w_in, t_w_out, s_w_in, s_w_out, ff_w1, ff_w2, w16);

    // --- temporal block ---
    gemm_f16<128, false, false, true><<<dim3(3, MB), 128, GEMM_SMEM_BYTES>>>(
        x16, w16 + W_T_IN, t_b_in, buf16, 384, nullptr, nullptr, nullptr, nullptr);
    temporal_attn<<<dim3(NS, BB), 96>>>(buf16, attn16);
    gemm_f16<128, false, true, false><<<dim3(1, MB), 128, GEMM_SMEM_BYTES>>>(
        attn16, w16 + W_T_OUT, t_b_out, x1, 128, x, norm_t_g, norm_t_b, x116);

    // --- spatial block ---
    gemm_f16<128, false, false, true><<<dim3(3, MB), 128, GEMM_SMEM_BYTES>>>(
        x116, w16 + W_S_IN, s_b_in, buf16, 384, nullptr, nullptr, nullptr, nullptr);
    spatial_attn_f16<<<dim3(8, BB * TT), 128>>>(buf16, g_bias, attn16);
    gemm_f16<128, false, true, false><<<dim3(1, MB), 128, GEMM_SMEM_BYTES>>>(
        attn16, w16 + W_S_OUT, s_b_out, x2, 128, x1, norm_s_g, norm_s_b, x216);

    // --- FFN ---
    gemm_f16<128, true, false, true><<<dim3(4, MB), 128, GEMM_SMEM_BYTES>>>(
        x216, w16 + W_FF1, ff_b1, h16, 512, nullptr, nullptr, nullptr, nullptr);
    gemm_f16<512, false, true, false><<<dim3(1, MB), 128, GEMM_SMEM_BYTES>>>(
        h16, w16 + W_FF2, ff_b2, out, 128, x2, norm_f_g, norm_f_b, nullptr);
}